// round 13
// baseline (speedup 1.0000x reference)
#include <cuda_runtime.h>
#include <math.h>
#include <stdint.h>

// ---------------------------------------------------------------------------
// Problem constants
// ---------------------------------------------------------------------------
namespace {
constexpr int B_ = 8, C_ = 256, H_ = 132, W_ = 132, NH_ = 8, D_ = 16;
constexpr int HW_ = H_ * W_;          // 17424
constexpr int M_  = B_ * HW_;         // 139392  (== 1089 * 128 exactly)
constexpr int CH_ = 128;              // C/2
constexpr int C2_ = 512;              // 2C
constexpr int C3_ = 384;              // 3C/2
constexpr int SPLIT_  = 8;
constexpr int KPS_    = HW_ / SPLIT_; // 2178 keys per split
constexpr int CHUNK_  = 66;           // keys per smem chunk (2178 = 33*66)
constexpr int NCHUNK_ = KPS_ / CHUNK_;
constexpr int KSTR_   = 20;           // smem row stride (floats), 16B-aligned

constexpr size_t SZ_BIG  = (size_t)M_ * C_;
constexpr size_t SZ_CAT  = (size_t)M_ * C3_;
constexpr size_t SZ_HALF = (size_t)M_ * CH_;

constexpr size_t OFF_XC    = 0;
constexpr size_t OFF_XEC   = OFF_XC  + SZ_BIG;
constexpr size_t OFF_XG    = OFF_XEC + SZ_BIG;
constexpr size_t OFF_KV    = OFF_XG  + SZ_BIG;
constexpr size_t OFF_CAT   = OFF_KV  + SZ_BIG;
constexpr size_t OFF_TQ    = OFF_CAT + SZ_CAT;      // [q_xc ; q_xec]   2M x 128
constexpr size_t OFF_TEF   = OFF_TQ  + 2 * SZ_HALF; // [ef_xec ; ef_xc] 2M x 128
constexpr size_t OFF_TCV   = OFF_TEF + 2 * SZ_HALF; // conv out         2M x 128
constexpr size_t OFF_POOL  = OFF_TCV + 2 * SZ_HALF;
constexpr size_t OFF_MM    = OFF_POOL  + (size_t)B_ * 36 * C2_;
constexpr size_t OFF_SMALL = OFF_MM    + (size_t)B_ * 36 * CH_;
constexpr size_t OFF_PMAX  = OFF_SMALL + (size_t)B_ * CH_ * 36;
constexpr size_t OFF_PSUM  = OFF_PMAX  + (size_t)B_ * NH_ * 36 * SPLIT_;
constexpr size_t OFF_PACC  = OFF_PSUM  + (size_t)B_ * NH_ * 36 * SPLIT_;
// transposed+tf32-rounded weights, [N][K] layout
constexpr size_t OFF_WBIG  = OFF_PACC  + (size_t)B_ * NH_ * 36 * SPLIT_ * D_;
constexpr size_t OFF_WKV   = OFF_WBIG  + 512 * 256;
constexpr size_t OFF_WEB   = OFF_WKV   + 256 * 256;
constexpr size_t OFF_WPROJ = OFF_WEB   + 128 * 128;
constexpr size_t OFF_BBIG  = OFF_WPROJ + 512 * 384;
constexpr size_t OFF_BQEF  = OFF_BBIG  + 512;
constexpr size_t OFF_BPROJ = OFF_BQEF  + 256;
constexpr size_t SCRATCH_TOTAL = OFF_BPROJ + 512;
}  // namespace

__device__ float g_scratch[SCRATCH_TOTAL];

// ---------------------------------------------------------------------------
// helpers
// ---------------------------------------------------------------------------
__device__ __forceinline__ float to_tf32(float x) {
    float r;
    asm("cvt.rna.tf32.f32 %0, %1;" : "=f"(r) : "f"(x));
    return r;
}
__device__ __forceinline__ void ldsm4(uint32_t& r0, uint32_t& r1, uint32_t& r2,
                                      uint32_t& r3, uint32_t addr) {
    asm volatile("ldmatrix.sync.aligned.m8n8.x4.shared.b16 {%0,%1,%2,%3}, [%4];"
                 : "=r"(r0), "=r"(r1), "=r"(r2), "=r"(r3) : "r"(addr));
}
__device__ __forceinline__ void cp_async16(uint32_t dst, const void* src) {
    asm volatile("cp.async.ca.shared.global [%0], [%1], 16;" :: "r"(dst), "l"(src));
}
__device__ __forceinline__ void cp_commit() {
    asm volatile("cp.async.commit_group;");
}
template <int N>
__device__ __forceinline__ void cp_wait() {
    asm volatile("cp.async.wait_group %0;" :: "n"(N));
}

// ---------------------------------------------------------------------------
// 0) weight prep (one-time per replay, tiny)
// ---------------------------------------------------------------------------
// wbig[N=512][K=256]: n<256 -> l_w, n<384 -> q_w, else ef_w
// NOTE: rows 256..511 double as the q|ef fused weight for the xec GEMM.
__global__ void tr_round3(const float* __restrict__ lw, const float* __restrict__ qw,
                          const float* __restrict__ efw, float* __restrict__ Wt)
{
    int i = blockIdx.x * 256 + threadIdx.x;
    if (i >= 256 * 512) return;
    int k = i >> 9, n = i & 511;
    float v;
    if (n < 256)      v = lw[k * 256 + n];
    else if (n < 384) v = qw[k * 128 + (n - 256)];
    else              v = efw[k * 128 + (n - 384)];
    Wt[(size_t)n * 256 + k] = to_tf32(v);
}
__global__ void tr_round(const float* __restrict__ W, float* __restrict__ Wt,
                         int K, int N)
{
    int i = blockIdx.x * 256 + threadIdx.x;
    if (i >= K * N) return;
    int k = i / N, n = i - k * N;
    Wt[(size_t)n * K + k] = to_tf32(W[i]);
}
// fuse two [K][Nh] weights into Wt[(2*Nh)][K]
__global__ void tr_round2(const float* __restrict__ W1, const float* __restrict__ W2,
                          float* __restrict__ Wt, int K, int Nh)
{
    int i = blockIdx.x * 256 + threadIdx.x;
    if (i >= K * 2 * Nh) return;
    int k = i / (2 * Nh), n = i - k * (2 * Nh);
    float v = (n < Nh) ? W1[k * Nh + n] : W2[k * Nh + (n - Nh)];
    Wt[(size_t)n * K + k] = to_tf32(v);
}
__global__ void prep_bias(const float* __restrict__ lb, const float* __restrict__ qb,
                          const float* __restrict__ efb,
                          const float* __restrict__ pb, const float* __restrict__ peb,
                          float* __restrict__ bbig, float* __restrict__ bqef,
                          float* __restrict__ bproj)
{
    int i = blockIdx.x * 256 + threadIdx.x;
    if (i < 512) {
        float v;
        if (i < 256)      v = lb[i];
        else if (i < 384) v = qb[i - 256];
        else              v = efb[i - 384];
        bbig[i] = v;
        bproj[i] = (i < 256) ? pb[i] : peb[i - 256];
    }
    if (i < 256) bqef[i] = (i < 128) ? qb[i] : efb[i - 128];
}

// ---------------------------------------------------------------------------
// 1) LayerNorm over channels, NCHW -> (B*HW, C); output tf32-rounded.
//    FUSED adaptive-pool accumulation via atomicAdd partials.
// ---------------------------------------------------------------------------
__global__ void ln_kernel(const float* __restrict__ x, const float* __restrict__ gw,
                          const float* __restrict__ gb, float* __restrict__ out,
                          float* __restrict__ pooled, int poolOff)
{
    __shared__ float s[256][33];
    __shared__ float sw[256], sb[256];
    int tid  = threadIdx.x;
    int b    = blockIdx.y;
    int pos0 = blockIdx.x * 32;
    sw[tid] = gw[tid];
    sb[tid] = gb[tid];
    int px = tid & 31, cg = tid >> 5;
    int p  = pos0 + px;
    const float* xb = x + (size_t)b * C_ * HW_;
    bool valid = (p < HW_);
    for (int c = cg; c < 256; c += 8)
        s[c][px] = valid ? xb[(size_t)c * HW_ + p] : 0.f;
    __syncthreads();
    int warp = tid >> 5, lane = tid & 31;
    float pr[8];
    int curbin = -1;
    #pragma unroll
    for (int jj = 0; jj < 8; ++jj) pr[jj] = 0.f;
    #pragma unroll
    for (int pi = 0; pi < 4; ++pi) {
        int pp = warp * 4 + pi;
        int gp = pos0 + pp;
        if (gp >= HW_) continue;
        float sum = 0.f, sum2 = 0.f;
        #pragma unroll
        for (int jj = 0; jj < 8; ++jj) {
            float v = s[lane + jj * 32][pp];
            sum += v; sum2 += v * v;
        }
        #pragma unroll
        for (int o = 16; o > 0; o >>= 1) {
            sum  += __shfl_xor_sync(0xffffffffu, sum,  o);
            sum2 += __shfl_xor_sync(0xffffffffu, sum2, o);
        }
        float mean = sum * (1.f / 256.f);
        float var  = fmaxf(sum2 * (1.f / 256.f) - mean * mean, 0.f);
        float rstd = rsqrtf(var + 1e-6f);
        float* orow = out + (size_t)(b * HW_ + gp) * 256;
        int h = gp / 132, w = gp - h * 132;
        int bin = (h / 22) * 6 + (w / 22);
        if (bin != curbin) {
            if (curbin >= 0) {
                float* pb = pooled + (size_t)(b * 36 + curbin) * 512 + poolOff + lane;
                #pragma unroll
                for (int jj = 0; jj < 8; ++jj)
                    atomicAdd(pb + jj * 32, pr[jj] * (1.f / 484.f));
            }
            curbin = bin;
            #pragma unroll
            for (int jj = 0; jj < 8; ++jj) pr[jj] = 0.f;
        }
        #pragma unroll
        for (int jj = 0; jj < 8; ++jj) {
            int c = lane + jj * 32;
            float v = to_tf32((s[c][pp] - mean) * rstd * sw[c] + sb[c]);
            orow[c] = v;
            pr[jj] += v;
        }
    }
    if (curbin >= 0) {
        float* pb = pooled + (size_t)(b * 36 + curbin) * 512 + poolOff + lane;
        #pragma unroll
        for (int jj = 0; jj < 8; ++jj)
            atomicAdd(pb + jj * 32, pr[jj] * (1.f / 484.f));
    }
}

// ---------------------------------------------------------------------------
// 2a) TF32 tensor-core GEMM, cp.async 4-stage pipeline + ldmatrix.
//     NEW: 4 warps (128 threads), warp tile 64x64 (2M x 2N) -> A/B each read
//     by only 2 warps: smem traffic 375 cyc/k16 < 512 compute cyc.
//     A[M][K] tf32-valued fp32; Wt[N][K] pre-rounded tf32.
//     BM=128 BN=128 BK=16. Smem [row][k0..15], chunk XOR swizzle.
//     EPI 0: plain row-major (ld 256)
//     EPI 4: dual NCHW split at col 256 (proj)
//     EPI 5: dual plain split at col 128
//     EPI 6: *aux, row-split (row<M_ -> cat col 128, else cat col 256)
//     EPI 7: triple: col<256 GELU->Cout(ld256); <384 ->Cout2; else ->Cout3
// ---------------------------------------------------------------------------
template <int EPI>
__global__ __launch_bounds__(128, 2)
void tgemm(const float* __restrict__ A, const float* __restrict__ Wt,
           const float* __restrict__ bias, const float* __restrict__ aux,
           float* __restrict__ Cout, float* __restrict__ Cout2,
           float* __restrict__ Cout3, int M, int N, int K)
{
    __shared__ float As[4][128 * 16];
    __shared__ float Bs[4][128 * 16];
    const int tid = threadIdx.x;
    const int bm = blockIdx.y * 128;
    const int bn = blockIdx.x * 128;
    const int lane = tid & 31, wid = tid >> 5;
    const int wm = (wid & 1) * 64, wn = (wid >> 1) * 64;
    const int g = lane >> 2, tig = lane & 3;

    float acc[4][8][4] = {};

    uint32_t sA = (uint32_t)__cvta_generic_to_shared(&As[0][0]);
    uint32_t sB = (uint32_t)__cvta_generic_to_shared(&Bs[0][0]);

    // ldmatrix fragment base addresses (buffer 0, k8 block 0); k8=1 -> ^32B
    uint32_t aAddr[4], bAddr[4];
    {
        int rsel = ((lane >> 3) & 1) * 8 + (lane & 7);
        int csel = lane >> 4;
        #pragma unroll
        for (int mt = 0; mt < 4; ++mt) {
            int row = wm + mt * 16 + rsel;
            int c = csel ^ ((row >> 1) & 3);
            aAddr[mt] = sA + (uint32_t)(row * 16 + 4 * c) * 4u;
        }
        int m = lane >> 3;
        int nrsel = (m >> 1) * 8 + (lane & 7);
        int ncsel = m & 1;
        #pragma unroll
        for (int np = 0; np < 4; ++np) {
            int row = wn + np * 16 + nrsel;
            int c = ncsel ^ ((row >> 1) & 3);
            bAddr[np] = sB + (uint32_t)(row * 16 + 4 * c) * 4u;
        }
    }

    // cp.async staging map: 128 threads, each moves 4 A + 4 B 16B chunks/stage
    const int aRow = tid >> 2;           // 0..31
    const int aK   = (tid & 3) << 2;     // 0,4,8,12
    int stf[4];
    const float *agp[4], *bgp[4];
    #pragma unroll
    for (int r = 0; r < 4; ++r) {
        int row = aRow + r * 32;
        stf[r] = row * 16 + 4 * ((aK >> 2) ^ ((row >> 1) & 3));
        agp[r] = A  + (size_t)(bm + row) * K + aK;
        bgp[r] = Wt + (size_t)(bn + row) * K + aK;
    }

    auto issue = [&](int s, int buf) {
        uint32_t off = (uint32_t)buf * 8192u;
        #pragma unroll
        for (int r = 0; r < 4; ++r) {
            cp_async16(sA + (uint32_t)stf[r] * 4u + off, agp[r] + s * 16);
            cp_async16(sB + (uint32_t)stf[r] * 4u + off, bgp[r] + s * 16);
        }
    };
    auto compute = [&](int buf) {
        uint32_t bo = (uint32_t)buf * 8192u;
        #pragma unroll
        for (int kb2 = 0; kb2 < 2; ++kb2) {
            uint32_t kx = kb2 ? 32u : 0u;
            uint32_t a_[4][4], b_[8][2];
            #pragma unroll
            for (int mt = 0; mt < 4; ++mt)
                ldsm4(a_[mt][0], a_[mt][1], a_[mt][2], a_[mt][3],
                      (aAddr[mt] + bo) ^ kx);
            #pragma unroll
            for (int np = 0; np < 4; ++np)
                ldsm4(b_[2 * np][0], b_[2 * np][1],
                      b_[2 * np + 1][0], b_[2 * np + 1][1],
                      (bAddr[np] + bo) ^ kx);
            #pragma unroll
            for (int mt = 0; mt < 4; ++mt)
                #pragma unroll
                for (int nt = 0; nt < 8; ++nt) {
                    asm volatile(
                        "mma.sync.aligned.m16n8k8.row.col.f32.tf32.tf32.f32 "
                        "{%0,%1,%2,%3}, {%4,%5,%6,%7}, {%8,%9}, {%0,%1,%2,%3};\n"
                        : "+f"(acc[mt][nt][0]), "+f"(acc[mt][nt][1]),
                          "+f"(acc[mt][nt][2]), "+f"(acc[mt][nt][3])
                        : "r"(a_[mt][0]), "r"(a_[mt][1]), "r"(a_[mt][2]), "r"(a_[mt][3]),
                          "r"(b_[nt][0]), "r"(b_[nt][1]));
                }
        }
    };

    const int nsteps = K >> 4;   // >= 8 for all our shapes
    issue(0, 0); cp_commit();
    issue(1, 1); cp_commit();
    issue(2, 2); cp_commit();
    cp_wait<2>();
    __syncthreads();
    for (int s = 0; s < nsteps; ++s) {
        compute(s & 3);
        if (s + 3 < nsteps) issue(s + 3, (s + 3) & 3);
        cp_commit();
        cp_wait<2>();
        __syncthreads();
    }

    // epilogue
    #pragma unroll
    for (int mt = 0; mt < 4; ++mt) {
        int row0 = bm + wm + mt * 16 + g;
        #pragma unroll
        for (int rr = 0; rr < 2; ++rr) {
            int row = row0 + rr * 8;
            #pragma unroll
            for (int nt = 0; nt < 8; ++nt) {
                #pragma unroll
                for (int cc = 0; cc < 2; ++cc) {
                    int col = bn + wn + nt * 8 + 2 * tig + cc;
                    float v = acc[mt][nt][rr * 2 + cc] + bias[col];
                    if (EPI == 0) {
                        Cout[(size_t)row * 256 + col] = v;
                    } else if (EPI == 4) {
                        int bb = row / HW_;
                        int pp = row - bb * HW_;
                        float* tgt = (col < 256) ? Cout : Cout2;
                        tgt[(size_t)(bb * 256 + (col & 255)) * HW_ + pp] = v;
                    } else if (EPI == 5) {
                        if (col < 128) Cout[(size_t)row * 128 + col] = v;
                        else           Cout2[(size_t)row * 128 + (col - 128)] = v;
                    } else if (EPI == 6) {
                        float vv = to_tf32(v * aux[(size_t)row * 128 + col]);
                        int r2 = row, co = 128;
                        if (r2 >= M_) { r2 -= M_; co = 256; }
                        Cout[(size_t)r2 * 384 + co + col] = vv;
                    } else if (EPI == 7) {
                        if (col < 256) {
                            float gl = 0.5f * v * (1.f + erff(v * 0.70710678f));
                            Cout[(size_t)row * 256 + col] = to_tf32(gl);
                        } else if (col < 384) {
                            Cout2[(size_t)row * 128 + (col - 256)] = v;
                        } else {
                            Cout3[(size_t)row * 128 + (col - 384)] = v;
                        }
                    }
                }
            }
        }
    }
}

// ---------------------------------------------------------------------------
// 2b) Small FFMA SGEMM (288-row pooled GEMM only; W is [K][N] original)
// ---------------------------------------------------------------------------
__global__ __launch_bounds__(256)
void sgemm_small(const float* __restrict__ A, const float* __restrict__ Wm,
                 const float* __restrict__ bias, float* __restrict__ Cout,
                 int M, int N, int K)
{
    __shared__ float As[16][132];
    __shared__ float Ws[16][64];
    int tid = threadIdx.x;
    int bm = blockIdx.y * 128;
    int bn = blockIdx.x * 64;
    int tx = tid & 15, ty = tid >> 4;
    float acc[8][4];
    #pragma unroll
    for (int i = 0; i < 8; ++i)
        #pragma unroll
        for (int j = 0; j < 4; ++j) acc[i][j] = 0.f;
    int aRow = tid >> 2;
    int aK   = (tid & 3) << 2;
    int wRow = tid >> 4;
    int wCol = (tid & 15) << 2;
    for (int k0 = 0; k0 < K; k0 += 16) {
        #pragma unroll
        for (int r = 0; r < 2; ++r) {
            int row = bm + aRow + r * 64;
            float4 v = make_float4(0.f, 0.f, 0.f, 0.f);
            if (row < M)
                v = *reinterpret_cast<const float4*>(A + (size_t)row * K + k0 + aK);
            As[aK + 0][aRow + r * 64] = v.x;
            As[aK + 1][aRow + r * 64] = v.y;
            As[aK + 2][aRow + r * 64] = v.z;
            As[aK + 3][aRow + r * 64] = v.w;
        }
        *reinterpret_cast<float4*>(&Ws[wRow][wCol]) =
            *reinterpret_cast<const float4*>(Wm + (size_t)(k0 + wRow) * N + bn + wCol);
        __syncthreads();
        #pragma unroll
        for (int kk = 0; kk < 16; ++kk) {
            float a[8], bf[4];
            #pragma unroll
            for (int i = 0; i < 8; ++i) a[i] = As[kk][ty * 8 + i];
            #pragma unroll
            for (int j = 0; j < 4; ++j) bf[j] = Ws[kk][tx * 4 + j];
            #pragma unroll
            for (int i = 0; i < 8; ++i)
                #pragma unroll
                for (int j = 0; j < 4; ++j)
                    acc[i][j] = fmaf(a[i], bf[j], acc[i][j]);
        }
        __syncthreads();
    }
    #pragma unroll
    for (int i = 0; i < 8; ++i) {
        int row = bm + ty * 8 + i;
        if (row >= M) continue;
        #pragma unroll
        for (int j = 0; j < 4; ++j) {
            int col = bn + tx * 4 + j;
            Cout[(size_t)row * N + col] = acc[i][j] + bias[col];
        }
    }
}

// ---------------------------------------------------------------------------
// 4) Attention (online softmax, split over keys) + combine.
//    K/V smem rows at stride KSTR_=20 floats (16B aligned) -> float4 loads.
// ---------------------------------------------------------------------------
__global__ __launch_bounds__(288)
void attn_partial(const float* __restrict__ kv, const float* __restrict__ mq_all,
                  float* __restrict__ pmax, float* __restrict__ psum,
                  float* __restrict__ pacc)
{
    __shared__ float ks[CHUNK_ * KSTR_];
    __shared__ float vs[CHUNK_ * KSTR_];
    int b = blockIdx.z, head = blockIdx.y, sp = blockIdx.x;
    int tid = threadIdx.x;
    int q = tid >> 3, j = tid & 7;
    float mq[16];
    #pragma unroll
    for (int d = 0; d < 16; ++d)
        mq[d] = mq_all[(size_t)(b * 36 + q) * 128 + head * 16 + d] * 0.25f;
    float mx = -INFINITY, sm = 0.f;
    float acc[16];
    #pragma unroll
    for (int d = 0; d < 16; ++d) acc[d] = 0.f;
    int kb = sp * KPS_;
    for (int c0 = 0; c0 < NCHUNK_; ++c0) {
        int pos0 = kb + c0 * CHUNK_;
        if (tid < CHUNK_ * 4) {
            int key = tid >> 2, d4 = tid & 3;
            size_t gb = ((size_t)b * HW_ + pos0 + key) * 256 + head * 16 + d4 * 4;
            *reinterpret_cast<float4*>(&ks[key * KSTR_ + d4 * 4]) =
                *reinterpret_cast<const float4*>(kv + gb);
            *reinterpret_cast<float4*>(&vs[key * KSTR_ + d4 * 4]) =
                *reinterpret_cast<const float4*>(kv + gb + 128);
        }
        __syncthreads();
        for (int key = j; key < CHUNK_; key += 8) {
            const float4* k4 = reinterpret_cast<const float4*>(&ks[key * KSTR_]);
            float4 ka = k4[0], kb2 = k4[1], kc = k4[2], kd = k4[3];
            float s = mq[0] * ka.x;
            s = fmaf(mq[1],  ka.y,  s); s = fmaf(mq[2],  ka.z,  s);
            s = fmaf(mq[3],  ka.w,  s); s = fmaf(mq[4],  kb2.x, s);
            s = fmaf(mq[5],  kb2.y, s); s = fmaf(mq[6],  kb2.z, s);
            s = fmaf(mq[7],  kb2.w, s); s = fmaf(mq[8],  kc.x,  s);
            s = fmaf(mq[9],  kc.y,  s); s = fmaf(mq[10], kc.z,  s);
            s = fmaf(mq[11], kc.w,  s); s = fmaf(mq[12], kd.x,  s);
            s = fmaf(mq[13], kd.y,  s); s = fmaf(mq[14], kd.z,  s);
            s = fmaf(mq[15], kd.w,  s);
            const float4* v4 = reinterpret_cast<const float4*>(&vs[key * KSTR_]);
            float4 va = v4[0], vb = v4[1], vc = v4[2], vd = v4[3];
            if (s <= mx) {
                float p = __expf(s - mx);
                sm += p;
                acc[0]  = fmaf(p, va.x, acc[0]);  acc[1]  = fmaf(p, va.y, acc[1]);
                acc[2]  = fmaf(p, va.z, acc[2]);  acc[3]  = fmaf(p, va.w, acc[3]);
                acc[4]  = fmaf(p, vb.x, acc[4]);  acc[5]  = fmaf(p, vb.y, acc[5]);
                acc[6]  = fmaf(p, vb.z, acc[6]);  acc[7]  = fmaf(p, vb.w, acc[7]);
                acc[8]  = fmaf(p, vc.x, acc[8]);  acc[9]  = fmaf(p, vc.y, acc[9]);
                acc[10] = fmaf(p, vc.z, acc[10]); acc[11] = fmaf(p, vc.w, acc[11]);
                acc[12] = fmaf(p, vd.x, acc[12]); acc[13] = fmaf(p, vd.y, acc[13]);
                acc[14] = fmaf(p, vd.z, acc[14]); acc[15] = fmaf(p, vd.w, acc[15]);
            } else {
                float cr = __expf(mx - s);
                sm = fmaf(sm, cr, 1.f);
                acc[0]  = fmaf(acc[0],  cr, va.x); acc[1]  = fmaf(acc[1],  cr, va.y);
                acc[2]  = fmaf(acc[2],  cr, va.z); acc[3]  = fmaf(acc[3],  cr, va.w);
                acc[4]  = fmaf(acc[4],  cr, vb.x); acc[5]  = fmaf(acc[5],  cr, vb.y);
                acc[6]  = fmaf(acc[6],  cr, vb.z); acc[7]  = fmaf(acc[7],  cr, vb.w);
                acc[8]  = fmaf(acc[8],  cr, vc.x); acc[9]  = fmaf(acc[9],  cr, vc.y);
                acc[10] = fmaf(acc[10], cr, vc.z); acc[11] = fmaf(acc[11], cr, vc.w);
                acc[12] = fmaf(acc[12], cr, vd.x); acc[13] = fmaf(acc[13], cr, vd.y);
                acc[14] = fmaf(acc[14], cr, vd.z); acc[15] = fmaf(acc[15], cr, vd.w);
                mx = s;
            }
        }
        __syncthreads();
    }
    #pragma unroll
    for (int o = 4; o > 0; o >>= 1) {
        float omx = __shfl_xor_sync(0xffffffffu, mx, o);
        float osm = __shfl_xor_sync(0xffffffffu, sm, o);
        float nm = fmaxf(mx, omx);
        float c1 = __expf(mx - nm), c2 = __expf(omx - nm);
        sm = sm * c1 + osm * c2;
        #pragma unroll
        for (int d = 0; d < 16; ++d) {
            float oa = __shfl_xor_sync(0xffffffffu, acc[d], o);
            acc[d] = acc[d] * c1 + oa * c2;
        }
        mx = nm;
    }
    int pi = (b * NH_ + head) * 36 + q;
    if (j == 0) {
        pmax[pi * SPLIT_ + sp] = mx;
        psum[pi * SPLIT_ + sp] = sm;
        #pragma unroll
        for (int d = 0; d < 16; ++d)
            pacc[((size_t)pi * SPLIT_ + sp) * 16 + d] = acc[d];
    }
}

__global__ void attn_combine(const float* __restrict__ pmax, const float* __restrict__ psum,
                             const float* __restrict__ pacc, float* __restrict__ sm_out)
{
    int idx = blockIdx.x * blockDim.x + threadIdx.x;
    if (idx >= B_ * NH_ * 36 * 16) return;
    int d  = idx & 15;
    int q  = (idx >> 4) % 36;
    int bh = idx / (16 * 36);
    int pi = bh * 36 + q;
    float gm = -INFINITY;
    #pragma unroll
    for (int s = 0; s < SPLIT_; ++s) gm = fmaxf(gm, pmax[pi * SPLIT_ + s]);
    float ts = 0.f, tv = 0.f;
    #pragma unroll
    for (int s = 0; s < SPLIT_; ++s) {
        float c = __expf(pmax[pi * SPLIT_ + s] - gm);
        ts += c * psum[pi * SPLIT_ + s];
        tv += c * pacc[((size_t)pi * SPLIT_ + s) * 16 + d];
    }
    int b = bh >> 3, head = bh & 7;
    sm_out[(size_t)(b * 128 + head * 16 + d) * 36 + q] = tv / ts;
}

// ---------------------------------------------------------------------------
// 5) Bilinear upsample (B,128,6,6) -> cat[:, 0:128], tf32-rounded
// ---------------------------------------------------------------------------
__global__ void upsample_kernel(const float* __restrict__ sm_in, float* __restrict__ cat)
{
    __shared__ float s[36][128];
    int b = blockIdx.y;
    for (int idx = threadIdx.x; idx < 36 * 128; idx += 128) {
        int q = idx >> 7, ch = idx & 127;
        s[q][ch] = sm_in[(size_t)(b * 128 + ch) * 36 + q];
    }
    __syncthreads();
    int ch = threadIdx.x;
    int p0 = blockIdx.x * 64;
    for (int k = 0; k < 64; ++k) {
        int p = p0 + k;
        if (p >= HW_) return;
        int h = p / 132, w = p - h * 132;
        float sy = (h + 0.5f) * (1.f / 22.f) - 0.5f;
        float sx = (w + 0.5f) * (1.f / 22.f) - 0.5f;
        float fy0 = floorf(sy), fx0 = floorf(sx);
        float fy = sy - fy0, fx = sx - fx0;
        int y0 = (int)fy0, x0 = (int)fx0;
        int y1 = min(y0 + 1, 5), x1 = min(x0 + 1, 5);
        y0 = max(y0, 0); x0 = max(x0, 0);
        float v00 = s[y0 * 6 + x0][ch], v01 = s[y0 * 6 + x1][ch];
        float v10 = s[y1 * 6 + x0][ch], v11 = s[y1 * 6 + x1][ch];
        float v = (1.f - fy) * ((1.f - fx) * v00 + fx * v01)
                + fy * ((1.f - fx) * v10 + fx * v11);
        cat[((size_t)b * HW_ + p) * 384 + ch] = to_tf32(v);
    }
}

// ---------------------------------------------------------------------------
// 6) Depthwise 7x7 conv, NHWC channels-inner, batched over 2B images;
//    output tf32-rounded
// ---------------------------------------------------------------------------
__global__ __launch_bounds__(256)
void dwconv_kernel(const float* __restrict__ in, const float* __restrict__ wgt,
                   const float* __restrict__ cbias, float* __restrict__ out)
{
    __shared__ float s[10][22][32];
    __shared__ float wsm[32][49];
    int wt = blockIdx.x, ht = blockIdx.y;
    int bz = blockIdx.z;
    int b = bz >> 2, cg = bz & 3;    // b in [0, 2*B_)
    int h0 = ht * 4, w0 = wt * 16;
    int tid = threadIdx.x;
    for (int idx = tid; idx < 32 * 49; idx += 256) {
        int ch = idx / 49, t = idx - ch * 49;
        wsm[ch][t] = wgt[(cg * 32 + ch) * 49 + t];
    }
    const float* inb = in + (size_t)b * HW_ * 128;
    for (int idx = tid; idx < 10 * 22 * 32; idx += 256) {
        int ch = idx & 31;
        int r  = idx >> 5;
        int lw = r % 22, lh = r / 22;
        int gh = h0 - 3 + lh, gw = w0 - 3 + lw;
        float v = 0.f;
        if (gh >= 0 && gh < 132 && gw >= 0 && gw < 132)
            v = inb[(size_t)(gh * 132 + gw) * 128 + cg * 32 + ch];
        s[lh][lw][ch] = v;
    }
    __syncthreads();
    int ch = tid & 31;
    int pg = tid >> 5;
    float acc[8];
    #pragma unroll
    for (int i = 0; i < 8; ++i) acc[i] = 0.f;
    #pragma unroll
    for (int dy = 0; dy < 7; ++dy)
        #pragma unroll
        for (int dx = 0; dx < 7; ++dx) {
            float wv = wsm[ch][dy * 7 + dx];
            #pragma unroll
            for (int pi = 0; pi < 8; ++pi) {
                int posid = pg + pi * 8;
                int lh = posid >> 4, lw = posid & 15;
                acc[pi] = fmaf(wv, s[lh + dy][lw + dx][ch], acc[pi]);
            }
        }
    float bv = cbias[cg * 32 + ch];
    #pragma unroll
    for (int pi = 0; pi < 8; ++pi) {
        int posid = pg + pi * 8;
        int lh = posid >> 4, lw = posid & 15;
        int gw = w0 + lw;
        if (gw < 132)
            out[((size_t)b * HW_ + (h0 + lh) * 132 + gw) * 128 + cg * 32 + ch]
                = to_tf32(acc[pi] + bv);
    }
}

// ---------------------------------------------------------------------------
// Launcher
// ---------------------------------------------------------------------------
extern "C" void kernel_launch(void* const* d_in, const int* in_sizes, int n_in,
                              void* d_out, int out_size)
{
    (void)in_sizes; (void)n_in; (void)out_size;
    const float* x       = (const float*)d_in[0];
    const float* x_e     = (const float*)d_in[1];
    const float* norm_w  = (const float*)d_in[2];
    const float* norm_b  = (const float*)d_in[3];
    const float* norme_w = (const float*)d_in[4];
    const float* norme_b = (const float*)d_in[5];
    const float* l_w     = (const float*)d_in[6];
    const float* l_b     = (const float*)d_in[7];
    const float* kv_w    = (const float*)d_in[8];
    const float* kv_b    = (const float*)d_in[9];
    const float* xe_w    = (const float*)d_in[10];
    const float* xe_b    = (const float*)d_in[11];
    const float* q_w     = (const float*)d_in[12];
    const float* q_b     = (const float*)d_in[13];
    const float* ef_w    = (const float*)d_in[14];
    const float* ef_b    = (const float*)d_in[15];
    const float* ec_w    = (const float*)d_in[16];
    const float* ec_b    = (const float*)d_in[17];
    const float* eb_w    = (const float*)d_in[18];
    const float* eb_b    = (const float*)d_in[19];
    const float* proj_w  = (const float*)d_in[20];
    const float* proj_b  = (const float*)d_in[21];
    const float* proje_w = (const float*)d_in[22];
    const float* proje_b = (const float*)d_in[23];

    float* base = nullptr;
    cudaGetSymbolAddress((void**)&base, g_scratch);
    float* xc    = base + OFF_XC;
    float* xec   = base + OFF_XEC;
    float* xg    = base + OFF_XG;
    float* kvb   = base + OFF_KV;
    float* cat   = base + OFF_CAT;
    float* tq    = base + OFF_TQ;    // [q_xc ; q_xec]
    float* tef   = base + OFF_TEF;   // [ef_xec ; ef_xc]
    float* tcv   = base + OFF_TCV;   // conv outputs, same row order as tef
    float* pool  = base + OFF_POOL;
    float* mbuf  = base + OFF_MM;
    float* smalb = base + OFF_SMALL;
    float* pmax  = base + OFF_PMAX;
    float* psum  = base + OFF_PSUM;
    float* pacc  = base + OFF_PACC;
    float* wbig  = base + OFF_WBIG;
    float* wkv_t = base + OFF_WKV;
    float* web_t = base + OFF_WEB;
    float* wproj_t = base + OFF_WPROJ;
    float* bbig  = base + OFF_BBIG;
    float* bqef  = base + OFF_BQEF;
    float* bproj = base + OFF_BPROJ;
    float* wqef_t = wbig + 256 * 256;   // rows 256..511 of wbig == q|ef fused

    float* outp = (float*)d_out;
    float* oute = outp + SZ_BIG;

    dim3 lnG((HW_ + 31) / 32, B_);

    // zero the pooled accumulator (graph-capturable async memset)
    cudaMemsetAsync(pool, 0, (size_t)B_ * 36 * 512 * sizeof(float));

    // weight/bias prep
    tr_round3<<<(256 * 512 + 255) / 256, 256>>>(l_w, q_w, ef_w, wbig);
    tr_round <<<(256 * 256 + 255) / 256, 256>>>(kv_w, wkv_t, 256, 256);
    prep_bias<<<2, 256>>>(l_b, q_b, ef_b, proj_b, proje_b, bbig, bqef, bproj);
    tr_round <<<(128 * 128 + 255) / 256, 256>>>(eb_w, web_t, 128, 128);
    tr_round2<<<(384 * 512 + 255) / 256, 256>>>(proj_w, proje_w, wproj_t, 384, 256);

    // LayerNorms with fused pooling accumulation
    ln_kernel<<<lnG, 256>>>(x,   norm_w,  norm_b,  xc,  pool, 0);
    ln_kernel<<<lnG, 256>>>(x_e, norme_w, norme_b, xec, pool, 256);

    // fused xc GEMM (N=512): gelu->xg | q_xc->tq[0:M] | ef_xc->tef[M:2M]
    tgemm<7><<<dim3(4, 1089), 128>>>(xc, wbig, bbig, nullptr,
                                     xg, tq, tef + SZ_HALF, M_, 512, 256);
    // kv GEMM
    tgemm<0><<<dim3(2, 1089), 128>>>(xg, wkv_t, kv_b, nullptr,
                                     kvb, nullptr, nullptr, M_, 256, 256);
    // xec q|ef GEMM: q_xec->tq[M:2M] | ef_xec->tef[0:M]
    tgemm<5><<<dim3(2, 1089), 128>>>(xec, wqef_t, bqef, nullptr,
                                     tq + SZ_HALF, tef, nullptr, M_, 256, 256);

    // GFA small path (pooled sums ready after LNs)
    sgemm_small<<<dim3(2, 3), 256>>>(pool, xe_w, xe_b, mbuf, B_ * 36, 128, 512);
    attn_partial<<<dim3(SPLIT_, NH_, B_), 288>>>(kvb, mbuf, pmax, psum, pacc);
    attn_combine<<<(B_ * NH_ * 36 * 16 + 255) / 256, 256>>>(pmax, psum, pacc, smalb);
    upsample_kernel<<<dim3((HW_ + 63) / 64, B_), 128>>>(smalb, cat);  // cat[:,0:128]

    // batched depthwise conv over both LFA inputs
    dwconv_kernel<<<dim3(9, 33, 2 * B_ * 4), 256>>>(tef, ec_w, ec_b, tcv);
    // merged eb GEMM (M=2M_), *q epilogue, row-split into cat cols 128/256
    tgemm<6><<<dim3(1, 2178), 128>>>(tcv, web_t, eb_b, tq,
                                     cat, nullptr, nullptr, 2 * M_, 128, 128);
    // fused projections, NCHW outputs split at col 256
    tgemm<4><<<dim3(4, 1089), 128>>>(cat, wproj_t, bproj, nullptr,
                                     outp, oute, nullptr, M_, 512, 384);
}

// round 15
// speedup vs baseline: 1.5831x; 1.5831x over previous
#include <cuda_runtime.h>
#include <math.h>
#include <stdint.h>

// ---------------------------------------------------------------------------
// Problem constants
// ---------------------------------------------------------------------------
namespace {
constexpr int B_ = 8, C_ = 256, H_ = 132, W_ = 132, NH_ = 8, D_ = 16;
constexpr int HW_ = H_ * W_;          // 17424
constexpr int M_  = B_ * HW_;         // 139392  (== 1089 * 128 exactly)
constexpr int CH_ = 128;              // C/2
constexpr int C2_ = 512;              // 2C
constexpr int C3_ = 384;              // 3C/2
constexpr int SPLIT_  = 8;
constexpr int KPS_    = HW_ / SPLIT_; // 2178 keys per split
constexpr int CHUNK_  = 66;           // keys per smem chunk (2178 = 33*66)
constexpr int NCHUNK_ = KPS_ / CHUNK_;
constexpr int KSTR_   = 20;           // smem row stride (floats), 16B-aligned

constexpr size_t SZ_BIG  = (size_t)M_ * C_;
constexpr size_t SZ_CAT  = (size_t)M_ * C3_;
constexpr size_t SZ_HALF = (size_t)M_ * CH_;

constexpr size_t OFF_XC    = 0;
constexpr size_t OFF_XEC   = OFF_XC  + SZ_BIG;
constexpr size_t OFF_XG    = OFF_XEC + SZ_BIG;
constexpr size_t OFF_KV    = OFF_XG  + SZ_BIG;
constexpr size_t OFF_CAT   = OFF_KV  + SZ_BIG;
constexpr size_t OFF_TQ    = OFF_CAT + SZ_CAT;      // [q_xc ; q_xec]   2M x 128
constexpr size_t OFF_TEF   = OFF_TQ  + 2 * SZ_HALF; // [ef_xec ; ef_xc] 2M x 128
constexpr size_t OFF_TCV   = OFF_TEF + 2 * SZ_HALF; // conv out         2M x 128
constexpr size_t OFF_POOL  = OFF_TCV + 2 * SZ_HALF;
constexpr size_t OFF_MM    = OFF_POOL  + (size_t)B_ * 36 * C2_;
constexpr size_t OFF_SMALL = OFF_MM    + (size_t)B_ * 36 * CH_;
constexpr size_t OFF_PMAX  = OFF_SMALL + (size_t)B_ * CH_ * 36;
constexpr size_t OFF_PSUM  = OFF_PMAX  + (size_t)B_ * NH_ * 36 * SPLIT_;
constexpr size_t OFF_PACC  = OFF_PSUM  + (size_t)B_ * NH_ * 36 * SPLIT_;
// transposed+tf32-rounded weights, [N][K] layout
constexpr size_t OFF_WBIG  = OFF_PACC  + (size_t)B_ * NH_ * 36 * SPLIT_ * D_;
constexpr size_t OFF_WKV   = OFF_WBIG  + 512 * 256;
constexpr size_t OFF_WEB   = OFF_WKV   + 256 * 256;
constexpr size_t OFF_WPROJ = OFF_WEB   + 128 * 128;
constexpr size_t OFF_BBIG  = OFF_WPROJ + 512 * 384;
constexpr size_t OFF_BQEF  = OFF_BBIG  + 512;
constexpr size_t OFF_BPROJ = OFF_BQEF  + 256;
constexpr size_t SCRATCH_TOTAL = OFF_BPROJ + 512;
}  // namespace

__device__ float g_scratch[SCRATCH_TOTAL];

// ---------------------------------------------------------------------------
// helpers
// ---------------------------------------------------------------------------
__device__ __forceinline__ float to_tf32(float x) {
    float r;
    asm("cvt.rna.tf32.f32 %0, %1;" : "=f"(r) : "f"(x));
    return r;
}
__device__ __forceinline__ void ldsm4(uint32_t& r0, uint32_t& r1, uint32_t& r2,
                                      uint32_t& r3, uint32_t addr) {
    asm volatile("ldmatrix.sync.aligned.m8n8.x4.shared.b16 {%0,%1,%2,%3}, [%4];"
                 : "=r"(r0), "=r"(r1), "=r"(r2), "=r"(r3) : "r"(addr));
}
__device__ __forceinline__ void cp_async16(uint32_t dst, const void* src) {
    asm volatile("cp.async.ca.shared.global [%0], [%1], 16;" :: "r"(dst), "l"(src));
}
__device__ __forceinline__ void cp_commit() {
    asm volatile("cp.async.commit_group;");
}
template <int N>
__device__ __forceinline__ void cp_wait() {
    asm volatile("cp.async.wait_group %0;" :: "n"(N));
}

// ---------------------------------------------------------------------------
// 0) weight prep (one-time per replay, tiny)
// ---------------------------------------------------------------------------
// wbig[N=512][K=256]: n<256 -> l_w, n<384 -> q_w, else ef_w
// NOTE: rows 256..511 double as the q|ef fused weight for the xec GEMM.
__global__ void tr_round3(const float* __restrict__ lw, const float* __restrict__ qw,
                          const float* __restrict__ efw, float* __restrict__ Wt)
{
    int i = blockIdx.x * 256 + threadIdx.x;
    if (i >= 256 * 512) return;
    int k = i >> 9, n = i & 511;
    float v;
    if (n < 256)      v = lw[k * 256 + n];
    else if (n < 384) v = qw[k * 128 + (n - 256)];
    else              v = efw[k * 128 + (n - 384)];
    Wt[(size_t)n * 256 + k] = to_tf32(v);
}
__global__ void tr_round(const float* __restrict__ W, float* __restrict__ Wt,
                         int K, int N)
{
    int i = blockIdx.x * 256 + threadIdx.x;
    if (i >= K * N) return;
    int k = i / N, n = i - k * N;
    Wt[(size_t)n * K + k] = to_tf32(W[i]);
}
// fuse two [K][Nh] weights into Wt[(2*Nh)][K]
__global__ void tr_round2(const float* __restrict__ W1, const float* __restrict__ W2,
                          float* __restrict__ Wt, int K, int Nh)
{
    int i = blockIdx.x * 256 + threadIdx.x;
    if (i >= K * 2 * Nh) return;
    int k = i / (2 * Nh), n = i - k * (2 * Nh);
    float v = (n < Nh) ? W1[k * Nh + n] : W2[k * Nh + (n - Nh)];
    Wt[(size_t)n * K + k] = to_tf32(v);
}
__global__ void prep_bias(const float* __restrict__ lb, const float* __restrict__ qb,
                          const float* __restrict__ efb,
                          const float* __restrict__ pb, const float* __restrict__ peb,
                          float* __restrict__ bbig, float* __restrict__ bqef,
                          float* __restrict__ bproj)
{
    int i = blockIdx.x * 256 + threadIdx.x;
    if (i < 512) {
        float v;
        if (i < 256)      v = lb[i];
        else if (i < 384) v = qb[i - 256];
        else              v = efb[i - 384];
        bbig[i] = v;
        bproj[i] = (i < 256) ? pb[i] : peb[i - 256];
    }
    if (i < 256) bqef[i] = (i < 128) ? qb[i] : efb[i - 128];
}

// ---------------------------------------------------------------------------
// 1) Dual LayerNorm over channels, NCHW -> (B*HW, C); output tf32-rounded.
//    blockIdx.z selects (x -> xc, poolOff 0) or (x_e -> xec, poolOff 256).
//    FUSED adaptive-pool accumulation via atomicAdd partials.
// ---------------------------------------------------------------------------
__global__ void ln2_kernel(const float* __restrict__ x0, const float* __restrict__ x1,
                           const float* __restrict__ gw0, const float* __restrict__ gb0,
                           const float* __restrict__ gw1, const float* __restrict__ gb1,
                           float* __restrict__ out0, float* __restrict__ out1,
                           float* __restrict__ pooled)
{
    __shared__ float s[256][33];
    __shared__ float sw[256], sb[256];
    int sel = blockIdx.z;
    const float* x  = sel ? x1  : x0;
    const float* gw = sel ? gw1 : gw0;
    const float* gb = sel ? gb1 : gb0;
    float* out      = sel ? out1 : out0;
    int poolOff     = sel * 256;
    int tid  = threadIdx.x;
    int b    = blockIdx.y;
    int pos0 = blockIdx.x * 32;
    sw[tid] = gw[tid];
    sb[tid] = gb[tid];
    int px = tid & 31, cg = tid >> 5;
    int p  = pos0 + px;
    const float* xb = x + (size_t)b * C_ * HW_;
    bool valid = (p < HW_);
    for (int c = cg; c < 256; c += 8)
        s[c][px] = valid ? xb[(size_t)c * HW_ + p] : 0.f;
    __syncthreads();
    int warp = tid >> 5, lane = tid & 31;
    float pr[8];
    int curbin = -1;
    #pragma unroll
    for (int jj = 0; jj < 8; ++jj) pr[jj] = 0.f;
    #pragma unroll
    for (int pi = 0; pi < 4; ++pi) {
        int pp = warp * 4 + pi;
        int gp = pos0 + pp;
        if (gp >= HW_) continue;
        float sum = 0.f, sum2 = 0.f;
        #pragma unroll
        for (int jj = 0; jj < 8; ++jj) {
            float v = s[lane + jj * 32][pp];
            sum += v; sum2 += v * v;
        }
        #pragma unroll
        for (int o = 16; o > 0; o >>= 1) {
            sum  += __shfl_xor_sync(0xffffffffu, sum,  o);
            sum2 += __shfl_xor_sync(0xffffffffu, sum2, o);
        }
        float mean = sum * (1.f / 256.f);
        float var  = fmaxf(sum2 * (1.f / 256.f) - mean * mean, 0.f);
        float rstd = rsqrtf(var + 1e-6f);
        float* orow = out + (size_t)(b * HW_ + gp) * 256;
        int h = gp / 132, w = gp - h * 132;
        int bin = (h / 22) * 6 + (w / 22);
        if (bin != curbin) {
            if (curbin >= 0) {
                float* pb = pooled + (size_t)(b * 36 + curbin) * 512 + poolOff + lane;
                #pragma unroll
                for (int jj = 0; jj < 8; ++jj)
                    atomicAdd(pb + jj * 32, pr[jj] * (1.f / 484.f));
            }
            curbin = bin;
            #pragma unroll
            for (int jj = 0; jj < 8; ++jj) pr[jj] = 0.f;
        }
        #pragma unroll
        for (int jj = 0; jj < 8; ++jj) {
            int c = lane + jj * 32;
            float v = to_tf32((s[c][pp] - mean) * rstd * sw[c] + sb[c]);
            orow[c] = v;
            pr[jj] += v;
        }
    }
    if (curbin >= 0) {
        float* pb = pooled + (size_t)(b * 36 + curbin) * 512 + poolOff + lane;
        #pragma unroll
        for (int jj = 0; jj < 8; ++jj)
            atomicAdd(pb + jj * 32, pr[jj] * (1.f / 484.f));
    }
}

// ---------------------------------------------------------------------------
// 2a) TF32 tensor-core GEMM, pure cp.async 4-stage pipeline + ldmatrix.
//     (proven round-11 configuration: 256 threads, warp tile 64x32 (2M x 4N),
//      prefetch distance 3, one commit/wait/sync per k16)
//     A[M][K]: values already tf32 (rna pre-rounded by producers).
//     Wt[N][K] pre-rounded tf32.
//     BM=128 BN=128 BK=16. Smem [row][k0..15], chunk XOR swizzle.
//     EPI 0: plain row-major (ld 256)
//     EPI 4: dual NCHW split at col 256 (proj)
//     EPI 5: dual plain split at col 128
//     EPI 6: *aux, row-split (row<M_ -> cat col 128, else cat col 256)
//     EPI 7: triple: col<256 GELU->Cout(ld256); <384 ->Cout2; else ->Cout3
// ---------------------------------------------------------------------------
template <int EPI>
__global__ __launch_bounds__(256, 2)
void tgemm(const float* __restrict__ A, const float* __restrict__ Wt,
           const float* __restrict__ bias, const float* __restrict__ aux,
           float* __restrict__ Cout, float* __restrict__ Cout2,
           float* __restrict__ Cout3, int M, int N, int K)
{
    __shared__ float As[4][128 * 16];
    __shared__ float Bs[4][128 * 16];
    const int tid = threadIdx.x;
    const int bm = blockIdx.y * 128;
    const int bn = blockIdx.x * 128;
    const int lane = tid & 31, wid = tid >> 5;
    const int wm = (wid & 1) * 64, wn = (wid >> 1) * 32;
    const int g = lane >> 2, tig = lane & 3;

    float acc[4][4][4] = {};

    uint32_t sA = (uint32_t)__cvta_generic_to_shared(&As[0][0]);
    uint32_t sB = (uint32_t)__cvta_generic_to_shared(&Bs[0][0]);

    // ldmatrix fragment base addresses (buffer 0, k8 block 0); k8=1 -> ^32B
    uint32_t aAddr[4], bAddr[2];
    {
        int rsel = ((lane >> 3) & 1) * 8 + (lane & 7);
        int csel = lane >> 4;
        #pragma unroll
        for (int mt = 0; mt < 4; ++mt) {
            int row = wm + mt * 16 + rsel;
            int c = csel ^ ((row >> 1) & 3);
            aAddr[mt] = sA + (uint32_t)(row * 16 + 4 * c) * 4u;
        }
        int m = lane >> 3;
        int nrsel = (m >> 1) * 8 + (lane & 7);
        int ncsel = m & 1;
        #pragma unroll
        for (int np = 0; np < 2; ++np) {
            int row = wn + np * 16 + nrsel;
            int c = ncsel ^ ((row >> 1) & 3);
            bAddr[np] = sB + (uint32_t)(row * 16 + 4 * c) * 4u;
        }
    }

    // cp.async staging map: each thread moves 2 A-chunks + 2 B-chunks per stage
    const int aRow = tid >> 2;           // 0..63
    const int aK   = (tid & 3) << 2;     // 0,4,8,12
    const int ar1  = aRow + 64;
    const int st0  = aRow * 16 + 4 * ((aK >> 2) ^ ((aRow >> 1) & 3));
    const int st1  = ar1 * 16 + 4 * ((aK >> 2) ^ ((ar1 >> 1) & 3));
    const float* agp0 = A  + (size_t)(bm + aRow) * K + aK;
    const float* agp1 = agp0 + (size_t)64 * K;
    const float* bgp0 = Wt + (size_t)(bn + aRow) * K + aK;
    const float* bgp1 = bgp0 + (size_t)64 * K;
    const uint32_t dA0 = sA + (uint32_t)st0 * 4u;
    const uint32_t dA1 = sA + (uint32_t)st1 * 4u;
    const uint32_t dB0 = sB + (uint32_t)st0 * 4u;
    const uint32_t dB1 = sB + (uint32_t)st1 * 4u;

    auto issue = [&](int s, int buf) {
        uint32_t off = (uint32_t)buf * 8192u;
        cp_async16(dA0 + off, agp0 + s * 16);
        cp_async16(dA1 + off, agp1 + s * 16);
        cp_async16(dB0 + off, bgp0 + s * 16);
        cp_async16(dB1 + off, bgp1 + s * 16);
    };
    auto compute = [&](int buf) {
        uint32_t bo = (uint32_t)buf * 8192u;
        #pragma unroll
        for (int kb2 = 0; kb2 < 2; ++kb2) {
            uint32_t kx = kb2 ? 32u : 0u;
            uint32_t a_[4][4], b_[4][2];
            #pragma unroll
            for (int mt = 0; mt < 4; ++mt)
                ldsm4(a_[mt][0], a_[mt][1], a_[mt][2], a_[mt][3],
                      (aAddr[mt] + bo) ^ kx);
            ldsm4(b_[0][0], b_[0][1], b_[1][0], b_[1][1], (bAddr[0] + bo) ^ kx);
            ldsm4(b_[2][0], b_[2][1], b_[3][0], b_[3][1], (bAddr[1] + bo) ^ kx);
            #pragma unroll
            for (int mt = 0; mt < 4; ++mt)
                #pragma unroll
                for (int nt = 0; nt < 4; ++nt) {
                    asm volatile(
                        "mma.sync.aligned.m16n8k8.row.col.f32.tf32.tf32.f32 "
                        "{%0,%1,%2,%3}, {%4,%5,%6,%7}, {%8,%9}, {%0,%1,%2,%3};\n"
                        : "+f"(acc[mt][nt][0]), "+f"(acc[mt][nt][1]),
                          "+f"(acc[mt][nt][2]), "+f"(acc[mt][nt][3])
                        : "r"(a_[mt][0]), "r"(a_[mt][1]), "r"(a_[mt][2]), "r"(a_[mt][3]),
                          "r"(b_[nt][0]), "r"(b_[nt][1]));
                }
        }
    };

    const int nsteps = K >> 4;   // >= 8 for all our shapes
    issue(0, 0); cp_commit();
    issue(1, 1); cp_commit();
    issue(2, 2); cp_commit();
    cp_wait<2>();
    __syncthreads();
    for (int s = 0; s < nsteps; ++s) {
        compute(s & 3);
        if (s + 3 < nsteps) issue(s + 3, (s + 3) & 3);
        cp_commit();
        cp_wait<2>();
        __syncthreads();
    }

    // epilogue
    #pragma unroll
    for (int mt = 0; mt < 4; ++mt) {
        int row0 = bm + wm + mt * 16 + g;
        #pragma unroll
        for (int rr = 0; rr < 2; ++rr) {
            int row = row0 + rr * 8;
            #pragma unroll
            for (int nt = 0; nt < 4; ++nt) {
                #pragma unroll
                for (int cc = 0; cc < 2; ++cc) {
                    int col = bn + wn + nt * 8 + 2 * tig + cc;
                    float v = acc[mt][nt][rr * 2 + cc] + bias[col];
                    if (EPI == 0) {
                        Cout[(size_t)row * 256 + col] = v;
                    } else if (EPI == 4) {
                        int bb = row / HW_;
                        int pp = row - bb * HW_;
                        float* tgt = (col < 256) ? Cout : Cout2;
                        tgt[(size_t)(bb * 256 + (col & 255)) * HW_ + pp] = v;
                    } else if (EPI == 5) {
                        if (col < 128) Cout[(size_t)row * 128 + col] = v;
                        else           Cout2[(size_t)row * 128 + (col - 128)] = v;
                    } else if (EPI == 6) {
                        float vv = to_tf32(v * aux[(size_t)row * 128 + col]);
                        int r2 = row, co = 128;
                        if (r2 >= M_) { r2 -= M_; co = 256; }
                        Cout[(size_t)r2 * 384 + co + col] = vv;
                    } else if (EPI == 7) {
                        if (col < 256) {
                            float gl = 0.5f * v * (1.f + erff(v * 0.70710678f));
                            Cout[(size_t)row * 256 + col] = to_tf32(gl);
                        } else if (col < 384) {
                            Cout2[(size_t)row * 128 + (col - 256)] = v;
                        } else {
                            Cout3[(size_t)row * 128 + (col - 384)] = v;
                        }
                    }
                }
            }
        }
    }
}

// ---------------------------------------------------------------------------
// 2b) Small FFMA SGEMM (288-row pooled GEMM only; W is [K][N] original)
// ---------------------------------------------------------------------------
__global__ __launch_bounds__(256)
void sgemm_small(const float* __restrict__ A, const float* __restrict__ Wm,
                 const float* __restrict__ bias, float* __restrict__ Cout,
                 int M, int N, int K)
{
    __shared__ float As[16][132];
    __shared__ float Ws[16][64];
    int tid = threadIdx.x;
    int bm = blockIdx.y * 128;
    int bn = blockIdx.x * 64;
    int tx = tid & 15, ty = tid >> 4;
    float acc[8][4];
    #pragma unroll
    for (int i = 0; i < 8; ++i)
        #pragma unroll
        for (int j = 0; j < 4; ++j) acc[i][j] = 0.f;
    int aRow = tid >> 2;
    int aK   = (tid & 3) << 2;
    int wRow = tid >> 4;
    int wCol = (tid & 15) << 2;
    for (int k0 = 0; k0 < K; k0 += 16) {
        #pragma unroll
        for (int r = 0; r < 2; ++r) {
            int row = bm + aRow + r * 64;
            float4 v = make_float4(0.f, 0.f, 0.f, 0.f);
            if (row < M)
                v = *reinterpret_cast<const float4*>(A + (size_t)row * K + k0 + aK);
            As[aK + 0][aRow + r * 64] = v.x;
            As[aK + 1][aRow + r * 64] = v.y;
            As[aK + 2][aRow + r * 64] = v.z;
            As[aK + 3][aRow + r * 64] = v.w;
        }
        *reinterpret_cast<float4*>(&Ws[wRow][wCol]) =
            *reinterpret_cast<const float4*>(Wm + (size_t)(k0 + wRow) * N + bn + wCol);
        __syncthreads();
        #pragma unroll
        for (int kk = 0; kk < 16; ++kk) {
            float a[8], bf[4];
            #pragma unroll
            for (int i = 0; i < 8; ++i) a[i] = As[kk][ty * 8 + i];
            #pragma unroll
            for (int j = 0; j < 4; ++j) bf[j] = Ws[kk][tx * 4 + j];
            #pragma unroll
            for (int i = 0; i < 8; ++i)
                #pragma unroll
                for (int j = 0; j < 4; ++j)
                    acc[i][j] = fmaf(a[i], bf[j], acc[i][j]);
        }
        __syncthreads();
    }
    #pragma unroll
    for (int i = 0; i < 8; ++i) {
        int row = bm + ty * 8 + i;
        if (row >= M) continue;
        #pragma unroll
        for (int j = 0; j < 4; ++j) {
            int col = bn + tx * 4 + j;
            Cout[(size_t)row * N + col] = acc[i][j] + bias[col];
        }
    }
}

// ---------------------------------------------------------------------------
// 4) Attention (online softmax, split over keys) + combine.
//    K/V smem rows at stride KSTR_=20 floats (16B aligned) -> float4 loads.
// ---------------------------------------------------------------------------
__global__ __launch_bounds__(288)
void attn_partial(const float* __restrict__ kv, const float* __restrict__ mq_all,
                  float* __restrict__ pmax, float* __restrict__ psum,
                  float* __restrict__ pacc)
{
    __shared__ float ks[CHUNK_ * KSTR_];
    __shared__ float vs[CHUNK_ * KSTR_];
    int b = blockIdx.z, head = blockIdx.y, sp = blockIdx.x;
    int tid = threadIdx.x;
    int q = tid >> 3, j = tid & 7;
    float mq[16];
    #pragma unroll
    for (int d = 0; d < 16; ++d)
        mq[d] = mq_all[(size_t)(b * 36 + q) * 128 + head * 16 + d] * 0.25f;
    float mx = -INFINITY, sm = 0.f;
    float acc[16];
    #pragma unroll
    for (int d = 0; d < 16; ++d) acc[d] = 0.f;
    int kb = sp * KPS_;
    for (int c0 = 0; c0 < NCHUNK_; ++c0) {
        int pos0 = kb + c0 * CHUNK_;
        if (tid < CHUNK_ * 4) {
            int key = tid >> 2, d4 = tid & 3;
            size_t gb = ((size_t)b * HW_ + pos0 + key) * 256 + head * 16 + d4 * 4;
            *reinterpret_cast<float4*>(&ks[key * KSTR_ + d4 * 4]) =
                *reinterpret_cast<const float4*>(kv + gb);
            *reinterpret_cast<float4*>(&vs[key * KSTR_ + d4 * 4]) =
                *reinterpret_cast<const float4*>(kv + gb + 128);
        }
        __syncthreads();
        for (int key = j; key < CHUNK_; key += 8) {
            const float4* k4 = reinterpret_cast<const float4*>(&ks[key * KSTR_]);
            float4 ka = k4[0], kb2 = k4[1], kc = k4[2], kd = k4[3];
            float s = mq[0] * ka.x;
            s = fmaf(mq[1],  ka.y,  s); s = fmaf(mq[2],  ka.z,  s);
            s = fmaf(mq[3],  ka.w,  s); s = fmaf(mq[4],  kb2.x, s);
            s = fmaf(mq[5],  kb2.y, s); s = fmaf(mq[6],  kb2.z, s);
            s = fmaf(mq[7],  kb2.w, s); s = fmaf(mq[8],  kc.x,  s);
            s = fmaf(mq[9],  kc.y,  s); s = fmaf(mq[10], kc.z,  s);
            s = fmaf(mq[11], kc.w,  s); s = fmaf(mq[12], kd.x,  s);
            s = fmaf(mq[13], kd.y,  s); s = fmaf(mq[14], kd.z,  s);
            s = fmaf(mq[15], kd.w,  s);
            const float4* v4 = reinterpret_cast<const float4*>(&vs[key * KSTR_]);
            float4 va = v4[0], vb = v4[1], vc = v4[2], vd = v4[3];
            if (s <= mx) {
                float p = __expf(s - mx);
                sm += p;
                acc[0]  = fmaf(p, va.x, acc[0]);  acc[1]  = fmaf(p, va.y, acc[1]);
                acc[2]  = fmaf(p, va.z, acc[2]);  acc[3]  = fmaf(p, va.w, acc[3]);
                acc[4]  = fmaf(p, vb.x, acc[4]);  acc[5]  = fmaf(p, vb.y, acc[5]);
                acc[6]  = fmaf(p, vb.z, acc[6]);  acc[7]  = fmaf(p, vb.w, acc[7]);
                acc[8]  = fmaf(p, vc.x, acc[8]);  acc[9]  = fmaf(p, vc.y, acc[9]);
                acc[10] = fmaf(p, vc.z, acc[10]); acc[11] = fmaf(p, vc.w, acc[11]);
                acc[12] = fmaf(p, vd.x, acc[12]); acc[13] = fmaf(p, vd.y, acc[13]);
                acc[14] = fmaf(p, vd.z, acc[14]); acc[15] = fmaf(p, vd.w, acc[15]);
            } else {
                float cr = __expf(mx - s);
                sm = fmaf(sm, cr, 1.f);
                acc[0]  = fmaf(acc[0],  cr, va.x); acc[1]  = fmaf(acc[1],  cr, va.y);
                acc[2]  = fmaf(acc[2],  cr, va.z); acc[3]  = fmaf(acc[3],  cr, va.w);
                acc[4]  = fmaf(acc[4],  cr, vb.x); acc[5]  = fmaf(acc[5],  cr, vb.y);
                acc[6]  = fmaf(acc[6],  cr, vb.z); acc[7]  = fmaf(acc[7],  cr, vb.w);
                acc[8]  = fmaf(acc[8],  cr, vc.x); acc[9]  = fmaf(acc[9],  cr, vc.y);
                acc[10] = fmaf(acc[10], cr, vc.z); acc[11] = fmaf(acc[11], cr, vc.w);
                acc[12] = fmaf(acc[12], cr, vd.x); acc[13] = fmaf(acc[13], cr, vd.y);
                acc[14] = fmaf(acc[14], cr, vd.z); acc[15] = fmaf(acc[15], cr, vd.w);
                mx = s;
            }
        }
        __syncthreads();
    }
    #pragma unroll
    for (int o = 4; o > 0; o >>= 1) {
        float omx = __shfl_xor_sync(0xffffffffu, mx, o);
        float osm = __shfl_xor_sync(0xffffffffu, sm, o);
        float nm = fmaxf(mx, omx);
        float c1 = __expf(mx - nm), c2 = __expf(omx - nm);
        sm = sm * c1 + osm * c2;
        #pragma unroll
        for (int d = 0; d < 16; ++d) {
            float oa = __shfl_xor_sync(0xffffffffu, acc[d], o);
            acc[d] = acc[d] * c1 + oa * c2;
        }
        mx = nm;
    }
    int pi = (b * NH_ + head) * 36 + q;
    if (j == 0) {
        pmax[pi * SPLIT_ + sp] = mx;
        psum[pi * SPLIT_ + sp] = sm;
        #pragma unroll
        for (int d = 0; d < 16; ++d)
            pacc[((size_t)pi * SPLIT_ + sp) * 16 + d] = acc[d];
    }
}

__global__ void attn_combine(const float* __restrict__ pmax, const float* __restrict__ psum,
                             const float* __restrict__ pacc, float* __restrict__ sm_out)
{
    int idx = blockIdx.x * blockDim.x + threadIdx.x;
    if (idx >= B_ * NH_ * 36 * 16) return;
    int d  = idx & 15;
    int q  = (idx >> 4) % 36;
    int bh = idx / (16 * 36);
    int pi = bh * 36 + q;
    float gm = -INFINITY;
    #pragma unroll
    for (int s = 0; s < SPLIT_; ++s) gm = fmaxf(gm, pmax[pi * SPLIT_ + s]);
    float ts = 0.f, tv = 0.f;
    #pragma unroll
    for (int s = 0; s < SPLIT_; ++s) {
        float c = __expf(pmax[pi * SPLIT_ + s] - gm);
        ts += c * psum[pi * SPLIT_ + s];
        tv += c * pacc[((size_t)pi * SPLIT_ + s) * 16 + d];
    }
    int b = bh >> 3, head = bh & 7;
    sm_out[(size_t)(b * 128 + head * 16 + d) * 36 + q] = tv / ts;
}

// ---------------------------------------------------------------------------
// 5) Bilinear upsample (B,128,6,6) -> cat[:, 0:128], tf32-rounded
// ---------------------------------------------------------------------------
__global__ void upsample_kernel(const float* __restrict__ sm_in, float* __restrict__ cat)
{
    __shared__ float s[36][128];
    int b = blockIdx.y;
    for (int idx = threadIdx.x; idx < 36 * 128; idx += 128) {
        int q = idx >> 7, ch = idx & 127;
        s[q][ch] = sm_in[(size_t)(b * 128 + ch) * 36 + q];
    }
    __syncthreads();
    int ch = threadIdx.x;
    int p0 = blockIdx.x * 64;
    for (int k = 0; k < 64; ++k) {
        int p = p0 + k;
        if (p >= HW_) return;
        int h = p / 132, w = p - h * 132;
        float sy = (h + 0.5f) * (1.f / 22.f) - 0.5f;
        float sx = (w + 0.5f) * (1.f / 22.f) - 0.5f;
        float fy0 = floorf(sy), fx0 = floorf(sx);
        float fy = sy - fy0, fx = sx - fx0;
        int y0 = (int)fy0, x0 = (int)fx0;
        int y1 = min(y0 + 1, 5), x1 = min(x0 + 1, 5);
        y0 = max(y0, 0); x0 = max(x0, 0);
        float v00 = s[y0 * 6 + x0][ch], v01 = s[y0 * 6 + x1][ch];
        float v10 = s[y1 * 6 + x0][ch], v11 = s[y1 * 6 + x1][ch];
        float v = (1.f - fy) * ((1.f - fx) * v00 + fx * v01)
                + fy * ((1.f - fx) * v10 + fx * v11);
        cat[((size_t)b * HW_ + p) * 384 + ch] = to_tf32(v);
    }
}

// ---------------------------------------------------------------------------
// 6) Depthwise 7x7 conv, NHWC channels-inner, batched over 2B images;
//    output tf32-rounded
// ---------------------------------------------------------------------------
__global__ __launch_bounds__(256)
void dwconv_kernel(const float* __restrict__ in, const float* __restrict__ wgt,
                   const float* __restrict__ cbias, float* __restrict__ out)
{
    __shared__ float s[10][22][32];
    __shared__ float wsm[32][49];
    int wt = blockIdx.x, ht = blockIdx.y;
    int bz = blockIdx.z;
    int b = bz >> 2, cg = bz & 3;    // b in [0, 2*B_)
    int h0 = ht * 4, w0 = wt * 16;
    int tid = threadIdx.x;
    for (int idx = tid; idx < 32 * 49; idx += 256) {
        int ch = idx / 49, t = idx - ch * 49;
        wsm[ch][t] = wgt[(cg * 32 + ch) * 49 + t];
    }
    const float* inb = in + (size_t)b * HW_ * 128;
    for (int idx = tid; idx < 10 * 22 * 32; idx += 256) {
        int ch = idx & 31;
        int r  = idx >> 5;
        int lw = r % 22, lh = r / 22;
        int gh = h0 - 3 + lh, gw = w0 - 3 + lw;
        float v = 0.f;
        if (gh >= 0 && gh < 132 && gw >= 0 && gw < 132)
            v = inb[(size_t)(gh * 132 + gw) * 128 + cg * 32 + ch];
        s[lh][lw][ch] = v;
    }
    __syncthreads();
    int ch = tid & 31;
    int pg = tid >> 5;
    float acc[8];
    #pragma unroll
    for (int i = 0; i < 8; ++i) acc[i] = 0.f;
    #pragma unroll
    for (int dy = 0; dy < 7; ++dy)
        #pragma unroll
        for (int dx = 0; dx < 7; ++dx) {
            float wv = wsm[ch][dy * 7 + dx];
            #pragma unroll
            for (int pi = 0; pi < 8; ++pi) {
                int posid = pg + pi * 8;
                int lh = posid >> 4, lw = posid & 15;
                acc[pi] = fmaf(wv, s[lh + dy][lw + dx][ch], acc[pi]);
            }
        }
    float bv = cbias[cg * 32 + ch];
    #pragma unroll
    for (int pi = 0; pi < 8; ++pi) {
        int posid = pg + pi * 8;
        int lh = posid >> 4, lw = posid & 15;
        int gw = w0 + lw;
        if (gw < 132)
            out[((size_t)b * HW_ + (h0 + lh) * 132 + gw) * 128 + cg * 32 + ch]
                = to_tf32(acc[pi] + bv);
    }
}

// ---------------------------------------------------------------------------
// Launcher
// ---------------------------------------------------------------------------
extern "C" void kernel_launch(void* const* d_in, const int* in_sizes, int n_in,
                              void* d_out, int out_size)
{
    (void)in_sizes; (void)n_in; (void)out_size;
    const float* x       = (const float*)d_in[0];
    const float* x_e     = (const float*)d_in[1];
    const float* norm_w  = (const float*)d_in[2];
    const float* norm_b  = (const float*)d_in[3];
    const float* norme_w = (const float*)d_in[4];
    const float* norme_b = (const float*)d_in[5];
    const float* l_w     = (const float*)d_in[6];
    const float* l_b     = (const float*)d_in[7];
    const float* kv_w    = (const float*)d_in[8];
    const float* kv_b    = (const float*)d_in[9];
    const float* xe_w    = (const float*)d_in[10];
    const float* xe_b    = (const float*)d_in[11];
    const float* q_w     = (const float*)d_in[12];
    const float* q_b     = (const float*)d_in[13];
    const float* ef_w    = (const float*)d_in[14];
    const float* ef_b    = (const float*)d_in[15];
    const float* ec_w    = (const float*)d_in[16];
    const float* ec_b    = (const float*)d_in[17];
    const float* eb_w    = (const float*)d_in[18];
    const float* eb_b    = (const float*)d_in[19];
    const float* proj_w  = (const float*)d_in[20];
    const float* proj_b  = (const float*)d_in[21];
    const float* proje_w = (const float*)d_in[22];
    const float* proje_b = (const float*)d_in[23];

    float* base = nullptr;
    cudaGetSymbolAddress((void**)&base, g_scratch);
    float* xc    = base + OFF_XC;
    float* xec   = base + OFF_XEC;
    float* xg    = base + OFF_XG;
    float* kvb   = base + OFF_KV;
    float* cat   = base + OFF_CAT;
    float* tq    = base + OFF_TQ;    // [q_xc ; q_xec]
    float* tef   = base + OFF_TEF;   // [ef_xec ; ef_xc]
    float* tcv   = base + OFF_TCV;   // conv outputs, same row order as tef
    float* pool  = base + OFF_POOL;
    float* mbuf  = base + OFF_MM;
    float* smalb = base + OFF_SMALL;
    float* pmax  = base + OFF_PMAX;
    float* psum  = base + OFF_PSUM;
    float* pacc  = base + OFF_PACC;
    float* wbig  = base + OFF_WBIG;
    float* wkv_t = base + OFF_WKV;
    float* web_t = base + OFF_WEB;
    float* wproj_t = base + OFF_WPROJ;
    float* bbig  = base + OFF_BBIG;
    float* bqef  = base + OFF_BQEF;
    float* bproj = base + OFF_BPROJ;
    float* wqef_t = wbig + 256 * 256;   // rows 256..511 of wbig == q|ef fused

    float* outp = (float*)d_out;
    float* oute = outp + SZ_BIG;

    dim3 lnG((HW_ + 31) / 32, B_, 2);

    // zero the pooled accumulator (graph-capturable async memset)
    cudaMemsetAsync(pool, 0, (size_t)B_ * 36 * 512 * sizeof(float));

    // weight/bias prep
    tr_round3<<<(256 * 512 + 255) / 256, 256>>>(l_w, q_w, ef_w, wbig);
    tr_round <<<(256 * 256 + 255) / 256, 256>>>(kv_w, wkv_t, 256, 256);
    prep_bias<<<2, 256>>>(l_b, q_b, ef_b, proj_b, proje_b, bbig, bqef, bproj);
    tr_round <<<(128 * 128 + 255) / 256, 256>>>(eb_w, web_t, 128, 128);
    tr_round2<<<(384 * 512 + 255) / 256, 256>>>(proj_w, proje_w, wproj_t, 384, 256);

    // Dual LayerNorm (x -> xc, x_e -> xec) with fused pooling accumulation
    ln2_kernel<<<lnG, 256>>>(x, x_e, norm_w, norm_b, norme_w, norme_b,
                             xc, xec, pool);

    // fused xc GEMM (N=512): gelu->xg | q_xc->tq[0:M] | ef_xc->tef[M:2M]
    tgemm<7><<<dim3(4, 1089), 256>>>(xc, wbig, bbig, nullptr,
                                     xg, tq, tef + SZ_HALF, M_, 512, 256);
    // kv GEMM
    tgemm<0><<<dim3(2, 1089), 256>>>(xg, wkv_t, kv_b, nullptr,
                                     kvb, nullptr, nullptr, M_, 256, 256);
    // xec q|ef GEMM: q_xec->tq[M:2M] | ef_xec->tef[0:M]
    tgemm<5><<<dim3(2, 1089), 256>>>(xec, wqef_t, bqef, nullptr,
                                     tq + SZ_HALF, tef, nullptr, M_, 256, 256);

    // GFA small path (pooled sums ready after LNs)
    sgemm_small<<<dim3(2, 3), 256>>>(pool, xe_w, xe_b, mbuf, B_ * 36, 128, 512);
    attn_partial<<<dim3(SPLIT_, NH_, B_), 288>>>(kvb, mbuf, pmax, psum, pacc);
    attn_combine<<<(B_ * NH_ * 36 * 16 + 255) / 256, 256>>>(pmax, psum, pacc, smalb);
    upsample_kernel<<<dim3((HW_ + 63) / 64, B_), 128>>>(smalb, cat);  // cat[:,0:128]

    // batched depthwise conv over both LFA inputs
    dwconv_kernel<<<dim3(9, 33, 2 * B_ * 4), 256>>>(tef, ec_w, ec_b, tcv);
    // merged eb GEMM (M=2M_), *q epilogue, row-split into cat cols 128/256
    tgemm<6><<<dim3(1, 2178), 256>>>(tcv, web_t, eb_b, tq,
                                     cat, nullptr, nullptr, 2 * M_, 128, 128);
    // fused projections, NCHW outputs split at col 256
    tgemm<4><<<dim3(4, 1089), 256>>>(cat, wproj_t, bproj, nullptr,
                                     outp, oute, nullptr, M_, 512, 384);
}

// round 16
// speedup vs baseline: 1.6912x; 1.0683x over previous
#include <cuda_runtime.h>
#include <math.h>
#include <stdint.h>

// ---------------------------------------------------------------------------
// Problem constants
// ---------------------------------------------------------------------------
namespace {
constexpr int B_ = 8, C_ = 256, H_ = 132, W_ = 132, NH_ = 8, D_ = 16;
constexpr int HW_ = H_ * W_;          // 17424
constexpr int M_  = B_ * HW_;         // 139392  (== 1089 * 128 exactly)
constexpr int CH_ = 128;              // C/2
constexpr int C2_ = 512;              // 2C
constexpr int C3_ = 384;              // 3C/2
constexpr int SPLIT_  = 8;
constexpr int KPS_    = HW_ / SPLIT_; // 2178 keys per split
constexpr int CHUNK_  = 66;           // keys per smem chunk (2178 = 33*66)
constexpr int NCHUNK_ = KPS_ / CHUNK_;
constexpr int KSTR_   = 20;           // smem row stride (floats), 16B-aligned

constexpr size_t SZ_BIG  = (size_t)M_ * C_;
constexpr size_t SZ_CAT  = (size_t)M_ * C3_;
constexpr size_t SZ_HALF = (size_t)M_ * CH_;

constexpr size_t OFF_XC    = 0;
constexpr size_t OFF_XEC   = OFF_XC  + SZ_BIG;
constexpr size_t OFF_XG    = OFF_XEC + SZ_BIG;
constexpr size_t OFF_KV    = OFF_XG  + SZ_BIG;
constexpr size_t OFF_CAT   = OFF_KV  + SZ_BIG;
constexpr size_t OFF_TQ    = OFF_CAT + SZ_CAT;      // [q_xc ; q_xec]   2M x 128
constexpr size_t OFF_TEF   = OFF_TQ  + 2 * SZ_HALF; // [ef_xec ; ef_xc] 2M x 128
constexpr size_t OFF_TCV   = OFF_TEF + 2 * SZ_HALF; // conv out         2M x 128
constexpr size_t OFF_POOL  = OFF_TCV + 2 * SZ_HALF;
constexpr size_t OFF_MM    = OFF_POOL  + (size_t)B_ * 36 * C2_;
constexpr size_t OFF_SMALL = OFF_MM    + (size_t)B_ * 36 * CH_;
constexpr size_t OFF_PMAX  = OFF_SMALL + (size_t)B_ * CH_ * 36;
constexpr size_t OFF_PSUM  = OFF_PMAX  + (size_t)B_ * NH_ * 36 * SPLIT_;
constexpr size_t OFF_PACC  = OFF_PSUM  + (size_t)B_ * NH_ * 36 * SPLIT_;
// transposed+tf32-rounded weights, [N][K] layout
constexpr size_t OFF_WBIG  = OFF_PACC  + (size_t)B_ * NH_ * 36 * SPLIT_ * D_;
constexpr size_t OFF_WKV   = OFF_WBIG  + 512 * 256;
constexpr size_t OFF_WEB   = OFF_WKV   + 256 * 256;
constexpr size_t OFF_WPROJ = OFF_WEB   + 128 * 128;
constexpr size_t OFF_BBIG  = OFF_WPROJ + 512 * 384;
constexpr size_t OFF_BQEF  = OFF_BBIG  + 512;
constexpr size_t OFF_BPROJ = OFF_BQEF  + 256;
constexpr size_t SCRATCH_TOTAL = OFF_BPROJ + 512;
}  // namespace

__device__ float g_scratch[SCRATCH_TOTAL];

// ---------------------------------------------------------------------------
// helpers
// ---------------------------------------------------------------------------
__device__ __forceinline__ float to_tf32(float x) {
    float r;
    asm("cvt.rna.tf32.f32 %0, %1;" : "=f"(r) : "f"(x));
    return r;
}
__device__ __forceinline__ void ldsm4(uint32_t& r0, uint32_t& r1, uint32_t& r2,
                                      uint32_t& r3, uint32_t addr) {
    asm volatile("ldmatrix.sync.aligned.m8n8.x4.shared.b16 {%0,%1,%2,%3}, [%4];"
                 : "=r"(r0), "=r"(r1), "=r"(r2), "=r"(r3) : "r"(addr));
}
__device__ __forceinline__ void cp_async16(uint32_t dst, const void* src) {
    asm volatile("cp.async.ca.shared.global [%0], [%1], 16;" :: "r"(dst), "l"(src));
}
__device__ __forceinline__ void cp_commit() {
    asm volatile("cp.async.commit_group;");
}
template <int N>
__device__ __forceinline__ void cp_wait() {
    asm volatile("cp.async.wait_group %0;" :: "n"(N));
}

// ---------------------------------------------------------------------------
// 0) weight prep (one-time per replay, tiny)
// ---------------------------------------------------------------------------
// wbig[N=512][K=256]: n<256 -> l_w, n<384 -> q_w, else ef_w
// NOTE: rows 256..511 double as the q|ef fused weight for the xec GEMM.
__global__ void tr_round3(const float* __restrict__ lw, const float* __restrict__ qw,
                          const float* __restrict__ efw, float* __restrict__ Wt)
{
    int i = blockIdx.x * 256 + threadIdx.x;
    if (i >= 256 * 512) return;
    int k = i >> 9, n = i & 511;
    float v;
    if (n < 256)      v = lw[k * 256 + n];
    else if (n < 384) v = qw[k * 128 + (n - 256)];
    else              v = efw[k * 128 + (n - 384)];
    Wt[(size_t)n * 256 + k] = to_tf32(v);
}
__global__ void tr_round(const float* __restrict__ W, float* __restrict__ Wt,
                         int K, int N)
{
    int i = blockIdx.x * 256 + threadIdx.x;
    if (i >= K * N) return;
    int k = i / N, n = i - k * N;
    Wt[(size_t)n * K + k] = to_tf32(W[i]);
}
// fuse two [K][Nh] weights into Wt[(2*Nh)][K]
__global__ void tr_round2(const float* __restrict__ W1, const float* __restrict__ W2,
                          float* __restrict__ Wt, int K, int Nh)
{
    int i = blockIdx.x * 256 + threadIdx.x;
    if (i >= K * 2 * Nh) return;
    int k = i / (2 * Nh), n = i - k * (2 * Nh);
    float v = (n < Nh) ? W1[k * Nh + n] : W2[k * Nh + (n - Nh)];
    Wt[(size_t)n * K + k] = to_tf32(v);
}
__global__ void prep_bias(const float* __restrict__ lb, const float* __restrict__ qb,
                          const float* __restrict__ efb,
                          const float* __restrict__ pb, const float* __restrict__ peb,
                          float* __restrict__ bbig, float* __restrict__ bqef,
                          float* __restrict__ bproj)
{
    int i = blockIdx.x * 256 + threadIdx.x;
    if (i < 512) {
        float v;
        if (i < 256)      v = lb[i];
        else if (i < 384) v = qb[i - 256];
        else              v = efb[i - 384];
        bbig[i] = v;
        bproj[i] = (i < 256) ? pb[i] : peb[i - 256];
    }
    if (i < 256) bqef[i] = (i < 128) ? qb[i] : efb[i - 128];
}

// ---------------------------------------------------------------------------
// 1) Dual LayerNorm over channels, NCHW -> (B*HW, C); output tf32-rounded.
//    blockIdx.z selects (x -> xc, poolOff 0) or (x_e -> xec, poolOff 256).
//    FUSED adaptive-pool accumulation via atomicAdd partials.
// ---------------------------------------------------------------------------
__global__ void ln2_kernel(const float* __restrict__ x0, const float* __restrict__ x1,
                           const float* __restrict__ gw0, const float* __restrict__ gb0,
                           const float* __restrict__ gw1, const float* __restrict__ gb1,
                           float* __restrict__ out0, float* __restrict__ out1,
                           float* __restrict__ pooled)
{
    __shared__ float s[256][33];
    __shared__ float sw[256], sb[256];
    int sel = blockIdx.z;
    const float* x  = sel ? x1  : x0;
    const float* gw = sel ? gw1 : gw0;
    const float* gb = sel ? gb1 : gb0;
    float* out      = sel ? out1 : out0;
    int poolOff     = sel * 256;
    int tid  = threadIdx.x;
    int b    = blockIdx.y;
    int pos0 = blockIdx.x * 32;
    sw[tid] = gw[tid];
    sb[tid] = gb[tid];
    int px = tid & 31, cg = tid >> 5;
    int p  = pos0 + px;
    const float* xb = x + (size_t)b * C_ * HW_;
    bool valid = (p < HW_);
    for (int c = cg; c < 256; c += 8)
        s[c][px] = valid ? xb[(size_t)c * HW_ + p] : 0.f;
    __syncthreads();
    int warp = tid >> 5, lane = tid & 31;
    float pr[8];
    int curbin = -1;
    #pragma unroll
    for (int jj = 0; jj < 8; ++jj) pr[jj] = 0.f;
    #pragma unroll
    for (int pi = 0; pi < 4; ++pi) {
        int pp = warp * 4 + pi;
        int gp = pos0 + pp;
        if (gp >= HW_) continue;
        float sum = 0.f, sum2 = 0.f;
        #pragma unroll
        for (int jj = 0; jj < 8; ++jj) {
            float v = s[lane + jj * 32][pp];
            sum += v; sum2 += v * v;
        }
        #pragma unroll
        for (int o = 16; o > 0; o >>= 1) {
            sum  += __shfl_xor_sync(0xffffffffu, sum,  o);
            sum2 += __shfl_xor_sync(0xffffffffu, sum2, o);
        }
        float mean = sum * (1.f / 256.f);
        float var  = fmaxf(sum2 * (1.f / 256.f) - mean * mean, 0.f);
        float rstd = rsqrtf(var + 1e-6f);
        float* orow = out + (size_t)(b * HW_ + gp) * 256;
        int h = gp / 132, w = gp - h * 132;
        int bin = (h / 22) * 6 + (w / 22);
        if (bin != curbin) {
            if (curbin >= 0) {
                float* pb = pooled + (size_t)(b * 36 + curbin) * 512 + poolOff + lane;
                #pragma unroll
                for (int jj = 0; jj < 8; ++jj)
                    atomicAdd(pb + jj * 32, pr[jj] * (1.f / 484.f));
            }
            curbin = bin;
            #pragma unroll
            for (int jj = 0; jj < 8; ++jj) pr[jj] = 0.f;
        }
        #pragma unroll
        for (int jj = 0; jj < 8; ++jj) {
            int c = lane + jj * 32;
            float v = to_tf32((s[c][pp] - mean) * rstd * sw[c] + sb[c]);
            orow[c] = v;
            pr[jj] += v;
        }
    }
    if (curbin >= 0) {
        float* pb = pooled + (size_t)(b * 36 + curbin) * 512 + poolOff + lane;
        #pragma unroll
        for (int jj = 0; jj < 8; ++jj)
            atomicAdd(pb + jj * 32, pr[jj] * (1.f / 484.f));
    }
}

// ---------------------------------------------------------------------------
// 2a) TF32 tensor-core GEMM, pure cp.async 4-stage pipeline + ldmatrix.
//     (proven configuration: 256 threads, warp tile 64x32 (2M x 4N),
//      prefetch distance 3, one commit/wait/sync per k16)
//     EPI 0: plain row-major (ld 256)
//     EPI 4: dual NCHW split at col 256 (proj)
//     EPI 5: dual plain split at col 128
//     EPI 6: *aux, row-split (row<M_ -> cat col 128, else cat col 256)
//     EPI 7: triple: col<256 GELU->Cout(ld256); <384 ->Cout2; else ->Cout3
// ---------------------------------------------------------------------------
template <int EPI>
__global__ __launch_bounds__(256, 2)
void tgemm(const float* __restrict__ A, const float* __restrict__ Wt,
           const float* __restrict__ bias, const float* __restrict__ aux,
           float* __restrict__ Cout, float* __restrict__ Cout2,
           float* __restrict__ Cout3, int M, int N, int K)
{
    __shared__ float As[4][128 * 16];
    __shared__ float Bs[4][128 * 16];
    const int tid = threadIdx.x;
    const int bm = blockIdx.y * 128;
    const int bn = blockIdx.x * 128;
    const int lane = tid & 31, wid = tid >> 5;
    const int wm = (wid & 1) * 64, wn = (wid >> 1) * 32;
    const int g = lane >> 2, tig = lane & 3;

    float acc[4][4][4] = {};

    uint32_t sA = (uint32_t)__cvta_generic_to_shared(&As[0][0]);
    uint32_t sB = (uint32_t)__cvta_generic_to_shared(&Bs[0][0]);

    // ldmatrix fragment base addresses (buffer 0, k8 block 0); k8=1 -> ^32B
    uint32_t aAddr[4], bAddr[2];
    {
        int rsel = ((lane >> 3) & 1) * 8 + (lane & 7);
        int csel = lane >> 4;
        #pragma unroll
        for (int mt = 0; mt < 4; ++mt) {
            int row = wm + mt * 16 + rsel;
            int c = csel ^ ((row >> 1) & 3);
            aAddr[mt] = sA + (uint32_t)(row * 16 + 4 * c) * 4u;
        }
        int m = lane >> 3;
        int nrsel = (m >> 1) * 8 + (lane & 7);
        int ncsel = m & 1;
        #pragma unroll
        for (int np = 0; np < 2; ++np) {
            int row = wn + np * 16 + nrsel;
            int c = ncsel ^ ((row >> 1) & 3);
            bAddr[np] = sB + (uint32_t)(row * 16 + 4 * c) * 4u;
        }
    }

    // cp.async staging map: each thread moves 2 A-chunks + 2 B-chunks per stage
    const int aRow = tid >> 2;           // 0..63
    const int aK   = (tid & 3) << 2;     // 0,4,8,12
    const int ar1  = aRow + 64;
    const int st0  = aRow * 16 + 4 * ((aK >> 2) ^ ((aRow >> 1) & 3));
    const int st1  = ar1 * 16 + 4 * ((aK >> 2) ^ ((ar1 >> 1) & 3));
    const float* agp0 = A  + (size_t)(bm + aRow) * K + aK;
    const float* agp1 = agp0 + (size_t)64 * K;
    const float* bgp0 = Wt + (size_t)(bn + aRow) * K + aK;
    const float* bgp1 = bgp0 + (size_t)64 * K;
    const uint32_t dA0 = sA + (uint32_t)st0 * 4u;
    const uint32_t dA1 = sA + (uint32_t)st1 * 4u;
    const uint32_t dB0 = sB + (uint32_t)st0 * 4u;
    const uint32_t dB1 = sB + (uint32_t)st1 * 4u;

    auto issue = [&](int s, int buf) {
        uint32_t off = (uint32_t)buf * 8192u;
        cp_async16(dA0 + off, agp0 + s * 16);
        cp_async16(dA1 + off, agp1 + s * 16);
        cp_async16(dB0 + off, bgp0 + s * 16);
        cp_async16(dB1 + off, bgp1 + s * 16);
    };
    auto compute = [&](int buf) {
        uint32_t bo = (uint32_t)buf * 8192u;
        #pragma unroll
        for (int kb2 = 0; kb2 < 2; ++kb2) {
            uint32_t kx = kb2 ? 32u : 0u;
            uint32_t a_[4][4], b_[4][2];
            #pragma unroll
            for (int mt = 0; mt < 4; ++mt)
                ldsm4(a_[mt][0], a_[mt][1], a_[mt][2], a_[mt][3],
                      (aAddr[mt] + bo) ^ kx);
            ldsm4(b_[0][0], b_[0][1], b_[1][0], b_[1][1], (bAddr[0] + bo) ^ kx);
            ldsm4(b_[2][0], b_[2][1], b_[3][0], b_[3][1], (bAddr[1] + bo) ^ kx);
            #pragma unroll
            for (int mt = 0; mt < 4; ++mt)
                #pragma unroll
                for (int nt = 0; nt < 4; ++nt) {
                    asm volatile(
                        "mma.sync.aligned.m16n8k8.row.col.f32.tf32.tf32.f32 "
                        "{%0,%1,%2,%3}, {%4,%5,%6,%7}, {%8,%9}, {%0,%1,%2,%3};\n"
                        : "+f"(acc[mt][nt][0]), "+f"(acc[mt][nt][1]),
                          "+f"(acc[mt][nt][2]), "+f"(acc[mt][nt][3])
                        : "r"(a_[mt][0]), "r"(a_[mt][1]), "r"(a_[mt][2]), "r"(a_[mt][3]),
                          "r"(b_[nt][0]), "r"(b_[nt][1]));
                }
        }
    };

    const int nsteps = K >> 4;   // >= 8 for all our shapes
    issue(0, 0); cp_commit();
    issue(1, 1); cp_commit();
    issue(2, 2); cp_commit();
    cp_wait<2>();
    __syncthreads();
    for (int s = 0; s < nsteps; ++s) {
        compute(s & 3);
        if (s + 3 < nsteps) issue(s + 3, (s + 3) & 3);
        cp_commit();
        cp_wait<2>();
        __syncthreads();
    }

    // epilogue
    #pragma unroll
    for (int mt = 0; mt < 4; ++mt) {
        int row0 = bm + wm + mt * 16 + g;
        #pragma unroll
        for (int rr = 0; rr < 2; ++rr) {
            int row = row0 + rr * 8;
            #pragma unroll
            for (int nt = 0; nt < 4; ++nt) {
                #pragma unroll
                for (int cc = 0; cc < 2; ++cc) {
                    int col = bn + wn + nt * 8 + 2 * tig + cc;
                    float v = acc[mt][nt][rr * 2 + cc] + bias[col];
                    if (EPI == 0) {
                        Cout[(size_t)row * 256 + col] = v;
                    } else if (EPI == 4) {
                        int bb = row / HW_;
                        int pp = row - bb * HW_;
                        float* tgt = (col < 256) ? Cout : Cout2;
                        tgt[(size_t)(bb * 256 + (col & 255)) * HW_ + pp] = v;
                    } else if (EPI == 5) {
                        if (col < 128) Cout[(size_t)row * 128 + col] = v;
                        else           Cout2[(size_t)row * 128 + (col - 128)] = v;
                    } else if (EPI == 6) {
                        float vv = to_tf32(v * aux[(size_t)row * 128 + col]);
                        int r2 = row, co = 128;
                        if (r2 >= M_) { r2 -= M_; co = 256; }
                        Cout[(size_t)r2 * 384 + co + col] = vv;
                    } else if (EPI == 7) {
                        if (col < 256) {
                            float gl = 0.5f * v * (1.f + erff(v * 0.70710678f));
                            Cout[(size_t)row * 256 + col] = to_tf32(gl);
                        } else if (col < 384) {
                            Cout2[(size_t)row * 128 + (col - 256)] = v;
                        } else {
                            Cout3[(size_t)row * 128 + (col - 384)] = v;
                        }
                    }
                }
            }
        }
    }
}

// ---------------------------------------------------------------------------
// 2b) Small FFMA SGEMM (288-row pooled GEMM only; W is [K][N] original)
// ---------------------------------------------------------------------------
__global__ __launch_bounds__(256)
void sgemm_small(const float* __restrict__ A, const float* __restrict__ Wm,
                 const float* __restrict__ bias, float* __restrict__ Cout,
                 int M, int N, int K)
{
    __shared__ float As[16][132];
    __shared__ float Ws[16][64];
    int tid = threadIdx.x;
    int bm = blockIdx.y * 128;
    int bn = blockIdx.x * 64;
    int tx = tid & 15, ty = tid >> 4;
    float acc[8][4];
    #pragma unroll
    for (int i = 0; i < 8; ++i)
        #pragma unroll
        for (int j = 0; j < 4; ++j) acc[i][j] = 0.f;
    int aRow = tid >> 2;
    int aK   = (tid & 3) << 2;
    int wRow = tid >> 4;
    int wCol = (tid & 15) << 2;
    for (int k0 = 0; k0 < K; k0 += 16) {
        #pragma unroll
        for (int r = 0; r < 2; ++r) {
            int row = bm + aRow + r * 64;
            float4 v = make_float4(0.f, 0.f, 0.f, 0.f);
            if (row < M)
                v = *reinterpret_cast<const float4*>(A + (size_t)row * K + k0 + aK);
            As[aK + 0][aRow + r * 64] = v.x;
            As[aK + 1][aRow + r * 64] = v.y;
            As[aK + 2][aRow + r * 64] = v.z;
            As[aK + 3][aRow + r * 64] = v.w;
        }
        *reinterpret_cast<float4*>(&Ws[wRow][wCol]) =
            *reinterpret_cast<const float4*>(Wm + (size_t)(k0 + wRow) * N + bn + wCol);
        __syncthreads();
        #pragma unroll
        for (int kk = 0; kk < 16; ++kk) {
            float a[8], bf[4];
            #pragma unroll
            for (int i = 0; i < 8; ++i) a[i] = As[kk][ty * 8 + i];
            #pragma unroll
            for (int j = 0; j < 4; ++j) bf[j] = Ws[kk][tx * 4 + j];
            #pragma unroll
            for (int i = 0; i < 8; ++i)
                #pragma unroll
                for (int j = 0; j < 4; ++j)
                    acc[i][j] = fmaf(a[i], bf[j], acc[i][j]);
        }
        __syncthreads();
    }
    #pragma unroll
    for (int i = 0; i < 8; ++i) {
        int row = bm + ty * 8 + i;
        if (row >= M) continue;
        #pragma unroll
        for (int j = 0; j < 4; ++j) {
            int col = bn + tx * 4 + j;
            Cout[(size_t)row * N + col] = acc[i][j] + bias[col];
        }
    }
}

// ---------------------------------------------------------------------------
// 4) Attention (online softmax, split over keys) + combine.
//    K/V smem rows at stride KSTR_=20 floats (16B aligned) -> float4 loads.
// ---------------------------------------------------------------------------
__global__ __launch_bounds__(288)
void attn_partial(const float* __restrict__ kv, const float* __restrict__ mq_all,
                  float* __restrict__ pmax, float* __restrict__ psum,
                  float* __restrict__ pacc)
{
    __shared__ float ks[CHUNK_ * KSTR_];
    __shared__ float vs[CHUNK_ * KSTR_];
    int b = blockIdx.z, head = blockIdx.y, sp = blockIdx.x;
    int tid = threadIdx.x;
    int q = tid >> 3, j = tid & 7;
    float mq[16];
    #pragma unroll
    for (int d = 0; d < 16; ++d)
        mq[d] = mq_all[(size_t)(b * 36 + q) * 128 + head * 16 + d] * 0.25f;
    float mx = -INFINITY, sm = 0.f;
    float acc[16];
    #pragma unroll
    for (int d = 0; d < 16; ++d) acc[d] = 0.f;
    int kb = sp * KPS_;
    for (int c0 = 0; c0 < NCHUNK_; ++c0) {
        int pos0 = kb + c0 * CHUNK_;
        if (tid < CHUNK_ * 4) {
            int key = tid >> 2, d4 = tid & 3;
            size_t gb = ((size_t)b * HW_ + pos0 + key) * 256 + head * 16 + d4 * 4;
            *reinterpret_cast<float4*>(&ks[key * KSTR_ + d4 * 4]) =
                *reinterpret_cast<const float4*>(kv + gb);
            *reinterpret_cast<float4*>(&vs[key * KSTR_ + d4 * 4]) =
                *reinterpret_cast<const float4*>(kv + gb + 128);
        }
        __syncthreads();
        for (int key = j; key < CHUNK_; key += 8) {
            const float4* k4 = reinterpret_cast<const float4*>(&ks[key * KSTR_]);
            float4 ka = k4[0], kb2 = k4[1], kc = k4[2], kd = k4[3];
            float s = mq[0] * ka.x;
            s = fmaf(mq[1],  ka.y,  s); s = fmaf(mq[2],  ka.z,  s);
            s = fmaf(mq[3],  ka.w,  s); s = fmaf(mq[4],  kb2.x, s);
            s = fmaf(mq[5],  kb2.y, s); s = fmaf(mq[6],  kb2.z, s);
            s = fmaf(mq[7],  kb2.w, s); s = fmaf(mq[8],  kc.x,  s);
            s = fmaf(mq[9],  kc.y,  s); s = fmaf(mq[10], kc.z,  s);
            s = fmaf(mq[11], kc.w,  s); s = fmaf(mq[12], kd.x,  s);
            s = fmaf(mq[13], kd.y,  s); s = fmaf(mq[14], kd.z,  s);
            s = fmaf(mq[15], kd.w,  s);
            const float4* v4 = reinterpret_cast<const float4*>(&vs[key * KSTR_]);
            float4 va = v4[0], vb = v4[1], vc = v4[2], vd = v4[3];
            if (s <= mx) {
                float p = __expf(s - mx);
                sm += p;
                acc[0]  = fmaf(p, va.x, acc[0]);  acc[1]  = fmaf(p, va.y, acc[1]);
                acc[2]  = fmaf(p, va.z, acc[2]);  acc[3]  = fmaf(p, va.w, acc[3]);
                acc[4]  = fmaf(p, vb.x, acc[4]);  acc[5]  = fmaf(p, vb.y, acc[5]);
                acc[6]  = fmaf(p, vb.z, acc[6]);  acc[7]  = fmaf(p, vb.w, acc[7]);
                acc[8]  = fmaf(p, vc.x, acc[8]);  acc[9]  = fmaf(p, vc.y, acc[9]);
                acc[10] = fmaf(p, vc.z, acc[10]); acc[11] = fmaf(p, vc.w, acc[11]);
                acc[12] = fmaf(p, vd.x, acc[12]); acc[13] = fmaf(p, vd.y, acc[13]);
                acc[14] = fmaf(p, vd.z, acc[14]); acc[15] = fmaf(p, vd.w, acc[15]);
            } else {
                float cr = __expf(mx - s);
                sm = fmaf(sm, cr, 1.f);
                acc[0]  = fmaf(acc[0],  cr, va.x); acc[1]  = fmaf(acc[1],  cr, va.y);
                acc[2]  = fmaf(acc[2],  cr, va.z); acc[3]  = fmaf(acc[3],  cr, va.w);
                acc[4]  = fmaf(acc[4],  cr, vb.x); acc[5]  = fmaf(acc[5],  cr, vb.y);
                acc[6]  = fmaf(acc[6],  cr, vb.z); acc[7]  = fmaf(acc[7],  cr, vb.w);
                acc[8]  = fmaf(acc[8],  cr, vc.x); acc[9]  = fmaf(acc[9],  cr, vc.y);
                acc[10] = fmaf(acc[10], cr, vc.z); acc[11] = fmaf(acc[11], cr, vc.w);
                acc[12] = fmaf(acc[12], cr, vd.x); acc[13] = fmaf(acc[13], cr, vd.y);
                acc[14] = fmaf(acc[14], cr, vd.z); acc[15] = fmaf(acc[15], cr, vd.w);
                mx = s;
            }
        }
        __syncthreads();
    }
    #pragma unroll
    for (int o = 4; o > 0; o >>= 1) {
        float omx = __shfl_xor_sync(0xffffffffu, mx, o);
        float osm = __shfl_xor_sync(0xffffffffu, sm, o);
        float nm = fmaxf(mx, omx);
        float c1 = __expf(mx - nm), c2 = __expf(omx - nm);
        sm = sm * c1 + osm * c2;
        #pragma unroll
        for (int d = 0; d < 16; ++d) {
            float oa = __shfl_xor_sync(0xffffffffu, acc[d], o);
            acc[d] = acc[d] * c1 + oa * c2;
        }
        mx = nm;
    }
    int pi = (b * NH_ + head) * 36 + q;
    if (j == 0) {
        pmax[pi * SPLIT_ + sp] = mx;
        psum[pi * SPLIT_ + sp] = sm;
        #pragma unroll
        for (int d = 0; d < 16; ++d)
            pacc[((size_t)pi * SPLIT_ + sp) * 16 + d] = acc[d];
    }
}

__global__ void attn_combine(const float* __restrict__ pmax, const float* __restrict__ psum,
                             const float* __restrict__ pacc, float* __restrict__ sm_out)
{
    int idx = blockIdx.x * blockDim.x + threadIdx.x;
    if (idx >= B_ * NH_ * 36 * 16) return;
    int d  = idx & 15;
    int q  = (idx >> 4) % 36;
    int bh = idx / (16 * 36);
    int pi = bh * 36 + q;
    float gm = -INFINITY;
    #pragma unroll
    for (int s = 0; s < SPLIT_; ++s) gm = fmaxf(gm, pmax[pi * SPLIT_ + s]);
    float ts = 0.f, tv = 0.f;
    #pragma unroll
    for (int s = 0; s < SPLIT_; ++s) {
        float c = __expf(pmax[pi * SPLIT_ + s] - gm);
        ts += c * psum[pi * SPLIT_ + s];
        tv += c * pacc[((size_t)pi * SPLIT_ + s) * 16 + d];
    }
    int b = bh >> 3, head = bh & 7;
    sm_out[(size_t)(b * 128 + head * 16 + d) * 36 + q] = tv / ts;
}

// ---------------------------------------------------------------------------
// 5) Bilinear upsample (B,128,6,6) -> cat[:, 0:128], tf32-rounded
// ---------------------------------------------------------------------------
__global__ void upsample_kernel(const float* __restrict__ sm_in, float* __restrict__ cat)
{
    __shared__ float s[36][128];
    int b = blockIdx.y;
    for (int idx = threadIdx.x; idx < 36 * 128; idx += 128) {
        int q = idx >> 7, ch = idx & 127;
        s[q][ch] = sm_in[(size_t)(b * 128 + ch) * 36 + q];
    }
    __syncthreads();
    int ch = threadIdx.x;
    int p0 = blockIdx.x * 64;
    for (int k = 0; k < 64; ++k) {
        int p = p0 + k;
        if (p >= HW_) return;
        int h = p / 132, w = p - h * 132;
        float sy = (h + 0.5f) * (1.f / 22.f) - 0.5f;
        float sx = (w + 0.5f) * (1.f / 22.f) - 0.5f;
        float fy0 = floorf(sy), fx0 = floorf(sx);
        float fy = sy - fy0, fx = sx - fx0;
        int y0 = (int)fy0, x0 = (int)fx0;
        int y1 = min(y0 + 1, 5), x1 = min(x0 + 1, 5);
        y0 = max(y0, 0); x0 = max(x0, 0);
        float v00 = s[y0 * 6 + x0][ch], v01 = s[y0 * 6 + x1][ch];
        float v10 = s[y1 * 6 + x0][ch], v11 = s[y1 * 6 + x1][ch];
        float v = (1.f - fy) * ((1.f - fx) * v00 + fx * v01)
                + fy * ((1.f - fx) * v10 + fx * v11);
        cat[((size_t)b * HW_ + p) * 384 + ch] = to_tf32(v);
    }
}

// ---------------------------------------------------------------------------
// 6) Depthwise 7x7 conv, NHWC channels-inner, batched over 2B images;
//    output tf32-rounded
// ---------------------------------------------------------------------------
__global__ __launch_bounds__(256)
void dwconv_kernel(const float* __restrict__ in, const float* __restrict__ wgt,
                   const float* __restrict__ cbias, float* __restrict__ out)
{
    __shared__ float s[10][22][32];
    __shared__ float wsm[32][49];
    int wt = blockIdx.x, ht = blockIdx.y;
    int bz = blockIdx.z;
    int b = bz >> 2, cg = bz & 3;    // b in [0, 2*B_)
    int h0 = ht * 4, w0 = wt * 16;
    int tid = threadIdx.x;
    for (int idx = tid; idx < 32 * 49; idx += 256) {
        int ch = idx / 49, t = idx - ch * 49;
        wsm[ch][t] = wgt[(cg * 32 + ch) * 49 + t];
    }
    const float* inb = in + (size_t)b * HW_ * 128;
    for (int idx = tid; idx < 10 * 22 * 32; idx += 256) {
        int ch = idx & 31;
        int r  = idx >> 5;
        int lw = r % 22, lh = r / 22;
        int gh = h0 - 3 + lh, gw = w0 - 3 + lw;
        float v = 0.f;
        if (gh >= 0 && gh < 132 && gw >= 0 && gw < 132)
            v = inb[(size_t)(gh * 132 + gw) * 128 + cg * 32 + ch];
        s[lh][lw][ch] = v;
    }
    __syncthreads();
    int ch = tid & 31;
    int pg = tid >> 5;
    float acc[8];
    #pragma unroll
    for (int i = 0; i < 8; ++i) acc[i] = 0.f;
    #pragma unroll
    for (int dy = 0; dy < 7; ++dy)
        #pragma unroll
        for (int dx = 0; dx < 7; ++dx) {
            float wv = wsm[ch][dy * 7 + dx];
            #pragma unroll
            for (int pi = 0; pi < 8; ++pi) {
                int posid = pg + pi * 8;
                int lh = posid >> 4, lw = posid & 15;
                acc[pi] = fmaf(wv, s[lh + dy][lw + dx][ch], acc[pi]);
            }
        }
    float bv = cbias[cg * 32 + ch];
    #pragma unroll
    for (int pi = 0; pi < 8; ++pi) {
        int posid = pg + pi * 8;
        int lh = posid >> 4, lw = posid & 15;
        int gw = w0 + lw;
        if (gw < 132)
            out[((size_t)b * HW_ + (h0 + lh) * 132 + gw) * 128 + cg * 32 + ch]
                = to_tf32(acc[pi] + bv);
    }
}

// ---------------------------------------------------------------------------
// Launcher — two-stream fork/join inside graph capture
// ---------------------------------------------------------------------------
extern "C" void kernel_launch(void* const* d_in, const int* in_sizes, int n_in,
                              void* d_out, int out_size)
{
    (void)in_sizes; (void)n_in; (void)out_size;
    const float* x       = (const float*)d_in[0];
    const float* x_e     = (const float*)d_in[1];
    const float* norm_w  = (const float*)d_in[2];
    const float* norm_b  = (const float*)d_in[3];
    const float* norme_w = (const float*)d_in[4];
    const float* norme_b = (const float*)d_in[5];
    const float* l_w     = (const float*)d_in[6];
    const float* l_b     = (const float*)d_in[7];
    const float* kv_w    = (const float*)d_in[8];
    const float* kv_b    = (const float*)d_in[9];
    const float* xe_w    = (const float*)d_in[10];
    const float* xe_b    = (const float*)d_in[11];
    const float* q_w     = (const float*)d_in[12];
    const float* q_b     = (const float*)d_in[13];
    const float* ef_w    = (const float*)d_in[14];
    const float* ef_b    = (const float*)d_in[15];
    const float* ec_w    = (const float*)d_in[16];
    const float* ec_b    = (const float*)d_in[17];
    const float* eb_w    = (const float*)d_in[18];
    const float* eb_b    = (const float*)d_in[19];
    const float* proj_w  = (const float*)d_in[20];
    const float* proj_b  = (const float*)d_in[21];
    const float* proje_w = (const float*)d_in[22];
    const float* proje_b = (const float*)d_in[23];

    float* base = nullptr;
    cudaGetSymbolAddress((void**)&base, g_scratch);
    float* xc    = base + OFF_XC;
    float* xec   = base + OFF_XEC;
    float* xg    = base + OFF_XG;
    float* kvb   = base + OFF_KV;
    float* cat   = base + OFF_CAT;
    float* tq    = base + OFF_TQ;    // [q_xc ; q_xec]
    float* tef   = base + OFF_TEF;   // [ef_xec ; ef_xc]
    float* tcv   = base + OFF_TCV;   // conv outputs, same row order as tef
    float* pool  = base + OFF_POOL;
    float* mbuf  = base + OFF_MM;
    float* smalb = base + OFF_SMALL;
    float* pmax  = base + OFF_PMAX;
    float* psum  = base + OFF_PSUM;
    float* pacc  = base + OFF_PACC;
    float* wbig  = base + OFF_WBIG;
    float* wkv_t = base + OFF_WKV;
    float* web_t = base + OFF_WEB;
    float* wproj_t = base + OFF_WPROJ;
    float* bbig  = base + OFF_BBIG;
    float* bqef  = base + OFF_BQEF;
    float* bproj = base + OFF_BPROJ;
    float* wqef_t = wbig + 256 * 256;   // rows 256..511 of wbig == q|ef fused

    float* outp = (float*)d_out;
    float* oute = outp + SZ_BIG;

    // side stream + events (host-side objects; created per call, not destroyed
    // because the capture that references them outlives this function)
    cudaStream_t s2;
    cudaStreamCreateWithFlags(&s2, cudaStreamNonBlocking);
    cudaEvent_t evFork, evPrep, evKV, evAttn;
    cudaEventCreateWithFlags(&evFork, cudaEventDisableTiming);
    cudaEventCreateWithFlags(&evPrep, cudaEventDisableTiming);
    cudaEventCreateWithFlags(&evKV,   cudaEventDisableTiming);
    cudaEventCreateWithFlags(&evAttn, cudaEventDisableTiming);

    dim3 lnG((HW_ + 31) / 32, B_, 2);

    // ---- fork 1: weight/bias prep on s2, overlapped with memset + LN -------
    cudaEventRecord(evFork, 0);
    cudaStreamWaitEvent(s2, evFork, 0);
    tr_round3<<<(256 * 512 + 255) / 256, 256, 0, s2>>>(l_w, q_w, ef_w, wbig);
    tr_round <<<(256 * 256 + 255) / 256, 256, 0, s2>>>(kv_w, wkv_t, 256, 256);
    prep_bias<<<2, 256, 0, s2>>>(l_b, q_b, ef_b, proj_b, proje_b, bbig, bqef, bproj);
    tr_round <<<(128 * 128 + 255) / 256, 256, 0, s2>>>(eb_w, web_t, 128, 128);
    tr_round2<<<(384 * 512 + 255) / 256, 256, 0, s2>>>(proj_w, proje_w, wproj_t, 384, 256);
    cudaEventRecord(evPrep, s2);

    // main: zero pooled accumulator + dual LayerNorm (independent of prep)
    cudaMemsetAsync(pool, 0, (size_t)B_ * 36 * 512 * sizeof(float));
    ln2_kernel<<<lnG, 256>>>(x, x_e, norm_w, norm_b, norme_w, norme_b,
                             xc, xec, pool);

    // join prep before the first GEMM that uses the transformed weights
    cudaStreamWaitEvent(0, evPrep, 0);

    // fused xc GEMM (N=512): gelu->xg | q_xc->tq[0:M] | ef_xc->tef[M:2M]
    tgemm<7><<<dim3(4, 1089), 256>>>(xc, wbig, bbig, nullptr,
                                     xg, tq, tef + SZ_HALF, M_, 512, 256);
    // kv GEMM
    tgemm<0><<<dim3(2, 1089), 256>>>(xg, wkv_t, kv_b, nullptr,
                                     kvb, nullptr, nullptr, M_, 256, 256);
    cudaEventRecord(evKV, 0);

    // ---- fork 2: GFA attention chain on s2 (needs pool + kvb only) --------
    cudaStreamWaitEvent(s2, evKV, 0);
    sgemm_small<<<dim3(2, 3), 256, 0, s2>>>(pool, xe_w, xe_b, mbuf,
                                            B_ * 36, 128, 512);
    attn_partial<<<dim3(SPLIT_, NH_, B_), 288, 0, s2>>>(kvb, mbuf,
                                                        pmax, psum, pacc);
    attn_combine<<<(B_ * NH_ * 36 * 16 + 255) / 256, 256, 0, s2>>>(
        pmax, psum, pacc, smalb);
    upsample_kernel<<<dim3((HW_ + 63) / 64, B_), 128, 0, s2>>>(smalb, cat);
    cudaEventRecord(evAttn, s2);

    // main (concurrent with s2): xec q|ef GEMM, batched dwconv, merged eb GEMM
    tgemm<5><<<dim3(2, 1089), 256>>>(xec, wqef_t, bqef, nullptr,
                                     tq + SZ_HALF, tef, nullptr, M_, 256, 256);
    dwconv_kernel<<<dim3(9, 33, 2 * B_ * 4), 256>>>(tef, ec_w, ec_b, tcv);
    tgemm<6><<<dim3(1, 2178), 256>>>(tcv, web_t, eb_b, tq,
                                     cat, nullptr, nullptr, 2 * M_, 128, 128);

    // join attention chain before the projections read all of cat
    cudaStreamWaitEvent(0, evAttn, 0);

    // fused projections, NCHW outputs split at col 256
    tgemm<4><<<dim3(4, 1089), 256>>>(cat, wproj_t, bproj, nullptr,
                                     outp, oute, nullptr, M_, 512, 384);
}

// round 17
// speedup vs baseline: 1.7762x; 1.0503x over previous
#include <cuda_runtime.h>
#include <math.h>
#include <stdint.h>

// ---------------------------------------------------------------------------
// Problem constants
// ---------------------------------------------------------------------------
namespace {
constexpr int B_ = 8, C_ = 256, H_ = 132, W_ = 132, NH_ = 8, D_ = 16;
constexpr int HW_ = H_ * W_;          // 17424
constexpr int M_  = B_ * HW_;         // 139392  (== 1089 * 128 exactly)
constexpr int CH_ = 128;              // C/2
constexpr int C2_ = 512;              // 2C
constexpr int C3_ = 384;              // 3C/2
constexpr int SPLIT_  = 8;
constexpr int KPS_    = HW_ / SPLIT_; // 2178 keys per split
constexpr int CHUNK_  = 66;           // keys per smem chunk (2178 = 33*66)
constexpr int NCHUNK_ = KPS_ / CHUNK_;
constexpr int KSTR_   = 20;           // smem row stride (floats), 16B-aligned

constexpr size_t SZ_BIG  = (size_t)M_ * C_;
constexpr size_t SZ_CAT  = (size_t)M_ * C3_;
constexpr size_t SZ_HALF = (size_t)M_ * CH_;

constexpr size_t OFF_XC    = 0;
constexpr size_t OFF_XEC   = OFF_XC  + SZ_BIG;
constexpr size_t OFF_XG    = OFF_XEC + SZ_BIG;
constexpr size_t OFF_KV    = OFF_XG  + SZ_BIG;
constexpr size_t OFF_CAT   = OFF_KV  + SZ_BIG;
constexpr size_t OFF_TQ    = OFF_CAT + SZ_CAT;      // [q_xc ; q_xec]   2M x 128
constexpr size_t OFF_TEF   = OFF_TQ  + 2 * SZ_HALF; // [ef_xec ; ef_xc] 2M x 128
constexpr size_t OFF_TCV   = OFF_TEF + 2 * SZ_HALF; // conv out         2M x 128
constexpr size_t OFF_POOL  = OFF_TCV + 2 * SZ_HALF;
constexpr size_t OFF_MM    = OFF_POOL  + (size_t)B_ * 36 * C2_;
constexpr size_t OFF_SMALL = OFF_MM    + (size_t)B_ * 36 * CH_;
constexpr size_t OFF_PMAX  = OFF_SMALL + (size_t)B_ * CH_ * 36;
constexpr size_t OFF_PSUM  = OFF_PMAX  + (size_t)B_ * NH_ * 36 * SPLIT_;
constexpr size_t OFF_PACC  = OFF_PSUM  + (size_t)B_ * NH_ * 36 * SPLIT_;
// transposed+tf32-rounded weights, [N][K] layout
constexpr size_t OFF_WBIG  = OFF_PACC  + (size_t)B_ * NH_ * 36 * SPLIT_ * D_;
constexpr size_t OFF_WKV   = OFF_WBIG  + 512 * 256;
constexpr size_t OFF_WEB   = OFF_WKV   + 256 * 256;
constexpr size_t OFF_WPROJ = OFF_WEB   + 128 * 128;
constexpr size_t OFF_BBIG  = OFF_WPROJ + 512 * 384;
constexpr size_t OFF_BQEF  = OFF_BBIG  + 512;
constexpr size_t OFF_BPROJ = OFF_BQEF  + 256;
constexpr size_t SCRATCH_TOTAL = OFF_BPROJ + 512;
}  // namespace

__device__ float g_scratch[SCRATCH_TOTAL];

// ---------------------------------------------------------------------------
// helpers
// ---------------------------------------------------------------------------
__device__ __forceinline__ float to_tf32(float x) {
    float r;
    asm("cvt.rna.tf32.f32 %0, %1;" : "=f"(r) : "f"(x));
    return r;
}
__device__ __forceinline__ void ldsm4(uint32_t& r0, uint32_t& r1, uint32_t& r2,
                                      uint32_t& r3, uint32_t addr) {
    asm volatile("ldmatrix.sync.aligned.m8n8.x4.shared.b16 {%0,%1,%2,%3}, [%4];"
                 : "=r"(r0), "=r"(r1), "=r"(r2), "=r"(r3) : "r"(addr));
}
__device__ __forceinline__ void cp_async16(uint32_t dst, const void* src) {
    asm volatile("cp.async.ca.shared.global [%0], [%1], 16;" :: "r"(dst), "l"(src));
}
__device__ __forceinline__ void cp_commit() {
    asm volatile("cp.async.commit_group;");
}
template <int N>
__device__ __forceinline__ void cp_wait() {
    asm volatile("cp.async.wait_group %0;" :: "n"(N));
}

// ---------------------------------------------------------------------------
// 0) weight prep (one-time per replay, tiny)
// ---------------------------------------------------------------------------
__global__ void tr_round3(const float* __restrict__ lw, const float* __restrict__ qw,
                          const float* __restrict__ efw, float* __restrict__ Wt)
{
    int i = blockIdx.x * 256 + threadIdx.x;
    if (i >= 256 * 512) return;
    int k = i >> 9, n = i & 511;
    float v;
    if (n < 256)      v = lw[k * 256 + n];
    else if (n < 384) v = qw[k * 128 + (n - 256)];
    else              v = efw[k * 128 + (n - 384)];
    Wt[(size_t)n * 256 + k] = to_tf32(v);
}
__global__ void tr_round(const float* __restrict__ W, float* __restrict__ Wt,
                         int K, int N)
{
    int i = blockIdx.x * 256 + threadIdx.x;
    if (i >= K * N) return;
    int k = i / N, n = i - k * N;
    Wt[(size_t)n * K + k] = to_tf32(W[i]);
}
__global__ void tr_round2(const float* __restrict__ W1, const float* __restrict__ W2,
                          float* __restrict__ Wt, int K, int Nh)
{
    int i = blockIdx.x * 256 + threadIdx.x;
    if (i >= K * 2 * Nh) return;
    int k = i / (2 * Nh), n = i - k * (2 * Nh);
    float v = (n < Nh) ? W1[k * Nh + n] : W2[k * Nh + (n - Nh)];
    Wt[(size_t)n * K + k] = to_tf32(v);
}
__global__ void prep_bias(const float* __restrict__ lb, const float* __restrict__ qb,
                          const float* __restrict__ efb,
                          const float* __restrict__ pb, const float* __restrict__ peb,
                          float* __restrict__ bbig, float* __restrict__ bqef,
                          float* __restrict__ bproj)
{
    int i = blockIdx.x * 256 + threadIdx.x;
    if (i < 512) {
        float v;
        if (i < 256)      v = lb[i];
        else if (i < 384) v = qb[i - 256];
        else              v = efb[i - 384];
        bbig[i] = v;
        bproj[i] = (i < 256) ? pb[i] : peb[i - 256];
    }
    if (i < 256) bqef[i] = (i < 128) ? qb[i] : efb[i - 128];
}

// ---------------------------------------------------------------------------
// 1) Dual LayerNorm (blockIdx.z selects input), fused pooling via atomicAdd
// ---------------------------------------------------------------------------
__global__ void ln2_kernel(const float* __restrict__ x0, const float* __restrict__ x1,
                           const float* __restrict__ gw0, const float* __restrict__ gb0,
                           const float* __restrict__ gw1, const float* __restrict__ gb1,
                           float* __restrict__ out0, float* __restrict__ out1,
                           float* __restrict__ pooled)
{
    __shared__ float s[256][33];
    __shared__ float sw[256], sb[256];
    int sel = blockIdx.z;
    const float* x  = sel ? x1  : x0;
    const float* gw = sel ? gw1 : gw0;
    const float* gb = sel ? gb1 : gb0;
    float* out      = sel ? out1 : out0;
    int poolOff     = sel * 256;
    int tid  = threadIdx.x;
    int b    = blockIdx.y;
    int pos0 = blockIdx.x * 32;
    sw[tid] = gw[tid];
    sb[tid] = gb[tid];
    int px = tid & 31, cg = tid >> 5;
    int p  = pos0 + px;
    const float* xb = x + (size_t)b * C_ * HW_;
    bool valid = (p < HW_);
    for (int c = cg; c < 256; c += 8)
        s[c][px] = valid ? xb[(size_t)c * HW_ + p] : 0.f;
    __syncthreads();
    int warp = tid >> 5, lane = tid & 31;
    float pr[8];
    int curbin = -1;
    #pragma unroll
    for (int jj = 0; jj < 8; ++jj) pr[jj] = 0.f;
    #pragma unroll
    for (int pi = 0; pi < 4; ++pi) {
        int pp = warp * 4 + pi;
        int gp = pos0 + pp;
        if (gp >= HW_) continue;
        float sum = 0.f, sum2 = 0.f;
        #pragma unroll
        for (int jj = 0; jj < 8; ++jj) {
            float v = s[lane + jj * 32][pp];
            sum += v; sum2 += v * v;
        }
        #pragma unroll
        for (int o = 16; o > 0; o >>= 1) {
            sum  += __shfl_xor_sync(0xffffffffu, sum,  o);
            sum2 += __shfl_xor_sync(0xffffffffu, sum2, o);
        }
        float mean = sum * (1.f / 256.f);
        float var  = fmaxf(sum2 * (1.f / 256.f) - mean * mean, 0.f);
        float rstd = rsqrtf(var + 1e-6f);
        float* orow = out + (size_t)(b * HW_ + gp) * 256;
        int h = gp / 132, w = gp - h * 132;
        int bin = (h / 22) * 6 + (w / 22);
        if (bin != curbin) {
            if (curbin >= 0) {
                float* pb = pooled + (size_t)(b * 36 + curbin) * 512 + poolOff + lane;
                #pragma unroll
                for (int jj = 0; jj < 8; ++jj)
                    atomicAdd(pb + jj * 32, pr[jj] * (1.f / 484.f));
            }
            curbin = bin;
            #pragma unroll
            for (int jj = 0; jj < 8; ++jj) pr[jj] = 0.f;
        }
        #pragma unroll
        for (int jj = 0; jj < 8; ++jj) {
            int c = lane + jj * 32;
            float v = to_tf32((s[c][pp] - mean) * rstd * sw[c] + sb[c]);
            orow[c] = v;
            pr[jj] += v;
        }
    }
    if (curbin >= 0) {
        float* pb = pooled + (size_t)(b * 36 + curbin) * 512 + poolOff + lane;
        #pragma unroll
        for (int jj = 0; jj < 8; ++jj)
            atomicAdd(pb + jj * 32, pr[jj] * (1.f / 484.f));
    }
}

// ---------------------------------------------------------------------------
// 2a) TF32 tensor-core GEMM, cp.async 4-stage + ldmatrix (proven config).
//     Epilogues use float2 stores (EPI 0/5/6/7) or per-warp smem-staged
//     coalesced NCHW stores (EPI 4).
// ---------------------------------------------------------------------------
template <int EPI>
__global__ __launch_bounds__(256, 2)
void tgemm(const float* __restrict__ A, const float* __restrict__ Wt,
           const float* __restrict__ bias, const float* __restrict__ aux,
           float* __restrict__ Cout, float* __restrict__ Cout2,
           float* __restrict__ Cout3, int M, int N, int K)
{
    __shared__ float As[4][128 * 16];
    __shared__ float Bs[4][128 * 16];
    const int tid = threadIdx.x;
    const int bm = blockIdx.y * 128;
    const int bn = blockIdx.x * 128;
    const int lane = tid & 31, wid = tid >> 5;
    const int wm = (wid & 1) * 64, wn = (wid >> 1) * 32;
    const int g = lane >> 2, tig = lane & 3;

    float acc[4][4][4] = {};

    uint32_t sA = (uint32_t)__cvta_generic_to_shared(&As[0][0]);
    uint32_t sB = (uint32_t)__cvta_generic_to_shared(&Bs[0][0]);

    uint32_t aAddr[4], bAddr[2];
    {
        int rsel = ((lane >> 3) & 1) * 8 + (lane & 7);
        int csel = lane >> 4;
        #pragma unroll
        for (int mt = 0; mt < 4; ++mt) {
            int row = wm + mt * 16 + rsel;
            int c = csel ^ ((row >> 1) & 3);
            aAddr[mt] = sA + (uint32_t)(row * 16 + 4 * c) * 4u;
        }
        int m = lane >> 3;
        int nrsel = (m >> 1) * 8 + (lane & 7);
        int ncsel = m & 1;
        #pragma unroll
        for (int np = 0; np < 2; ++np) {
            int row = wn + np * 16 + nrsel;
            int c = ncsel ^ ((row >> 1) & 3);
            bAddr[np] = sB + (uint32_t)(row * 16 + 4 * c) * 4u;
        }
    }

    const int aRow = tid >> 2;
    const int aK   = (tid & 3) << 2;
    const int ar1  = aRow + 64;
    const int st0  = aRow * 16 + 4 * ((aK >> 2) ^ ((aRow >> 1) & 3));
    const int st1  = ar1 * 16 + 4 * ((aK >> 2) ^ ((ar1 >> 1) & 3));
    const float* agp0 = A  + (size_t)(bm + aRow) * K + aK;
    const float* agp1 = agp0 + (size_t)64 * K;
    const float* bgp0 = Wt + (size_t)(bn + aRow) * K + aK;
    const float* bgp1 = bgp0 + (size_t)64 * K;
    const uint32_t dA0 = sA + (uint32_t)st0 * 4u;
    const uint32_t dA1 = sA + (uint32_t)st1 * 4u;
    const uint32_t dB0 = sB + (uint32_t)st0 * 4u;
    const uint32_t dB1 = sB + (uint32_t)st1 * 4u;

    auto issue = [&](int s, int buf) {
        uint32_t off = (uint32_t)buf * 8192u;
        cp_async16(dA0 + off, agp0 + s * 16);
        cp_async16(dA1 + off, agp1 + s * 16);
        cp_async16(dB0 + off, bgp0 + s * 16);
        cp_async16(dB1 + off, bgp1 + s * 16);
    };
    auto compute = [&](int buf) {
        uint32_t bo = (uint32_t)buf * 8192u;
        #pragma unroll
        for (int kb2 = 0; kb2 < 2; ++kb2) {
            uint32_t kx = kb2 ? 32u : 0u;
            uint32_t a_[4][4], b_[4][2];
            #pragma unroll
            for (int mt = 0; mt < 4; ++mt)
                ldsm4(a_[mt][0], a_[mt][1], a_[mt][2], a_[mt][3],
                      (aAddr[mt] + bo) ^ kx);
            ldsm4(b_[0][0], b_[0][1], b_[1][0], b_[1][1], (bAddr[0] + bo) ^ kx);
            ldsm4(b_[2][0], b_[2][1], b_[3][0], b_[3][1], (bAddr[1] + bo) ^ kx);
            #pragma unroll
            for (int mt = 0; mt < 4; ++mt)
                #pragma unroll
                for (int nt = 0; nt < 4; ++nt) {
                    asm volatile(
                        "mma.sync.aligned.m16n8k8.row.col.f32.tf32.tf32.f32 "
                        "{%0,%1,%2,%3}, {%4,%5,%6,%7}, {%8,%9}, {%0,%1,%2,%3};\n"
                        : "+f"(acc[mt][nt][0]), "+f"(acc[mt][nt][1]),
                          "+f"(acc[mt][nt][2]), "+f"(acc[mt][nt][3])
                        : "r"(a_[mt][0]), "r"(a_[mt][1]), "r"(a_[mt][2]), "r"(a_[mt][3]),
                          "r"(b_[nt][0]), "r"(b_[nt][1]));
                }
        }
    };

    const int nsteps = K >> 4;
    issue(0, 0); cp_commit();
    issue(1, 1); cp_commit();
    issue(2, 2); cp_commit();
    cp_wait<2>();
    __syncthreads();
    for (int s = 0; s < nsteps; ++s) {
        compute(s & 3);
        if (s + 3 < nsteps) issue(s + 3, (s + 3) & 3);
        cp_commit();
        cp_wait<2>();
        __syncthreads();
    }

    if (EPI == 4) {
        // per-warp smem-staged transposed (NCHW) store.
        // warp tile = 64 rows x 32 cols; stage as wt[col(32)][row(64)].
        float* wt = &As[0][0] + wid * 2048;
        #pragma unroll
        for (int mt = 0; mt < 4; ++mt)
            #pragma unroll
            for (int nt = 0; nt < 4; ++nt)
                #pragma unroll
                for (int rr = 0; rr < 2; ++rr)
                    #pragma unroll
                    for (int cc = 0; cc < 2; ++cc) {
                        int lr = mt * 16 + g + rr * 8;
                        int lc = nt * 8 + 2 * tig + cc;
                        wt[lc * 64 + lr] = acc[mt][nt][rr * 2 + cc]
                                         + bias[bn + wn + lc];
                    }
        __syncwarp();
        int grow0 = bm + wm + lane;
        int grow1 = grow0 + 32;
        int bb0 = grow0 / HW_, pp0 = grow0 - bb0 * HW_;
        int bb1 = grow1 / HW_, pp1 = grow1 - bb1 * HW_;
        #pragma unroll 4
        for (int lc = 0; lc < 32; ++lc) {
            int col = bn + wn + lc;
            float* tgt = (col < 256) ? Cout : Cout2;
            int ch = col & 255;
            tgt[(size_t)(bb0 * 256 + ch) * HW_ + pp0] = wt[lc * 64 + lane];
            tgt[(size_t)(bb1 * 256 + ch) * HW_ + pp1] = wt[lc * 64 + lane + 32];
        }
        return;
    }

    // float2 epilogues (row-major layouts)
    #pragma unroll
    for (int mt = 0; mt < 4; ++mt) {
        int row0 = bm + wm + mt * 16 + g;
        #pragma unroll
        for (int rr = 0; rr < 2; ++rr) {
            int row = row0 + rr * 8;
            #pragma unroll
            for (int nt = 0; nt < 4; ++nt) {
                int colb = bn + wn + nt * 8 + 2 * tig;
                float v0 = acc[mt][nt][rr * 2 + 0] + bias[colb];
                float v1 = acc[mt][nt][rr * 2 + 1] + bias[colb + 1];
                if (EPI == 0) {
                    *reinterpret_cast<float2*>(&Cout[(size_t)row * 256 + colb])
                        = make_float2(v0, v1);
                } else if (EPI == 5) {
                    if (colb < 128)
                        *reinterpret_cast<float2*>(&Cout[(size_t)row * 128 + colb])
                            = make_float2(v0, v1);
                    else
                        *reinterpret_cast<float2*>(&Cout2[(size_t)row * 128 + colb - 128])
                            = make_float2(v0, v1);
                } else if (EPI == 6) {
                    float2 ax = *reinterpret_cast<const float2*>(
                        &aux[(size_t)row * 128 + colb]);
                    v0 = to_tf32(v0 * ax.x);
                    v1 = to_tf32(v1 * ax.y);
                    int r2 = row, co = 128;
                    if (r2 >= M_) { r2 -= M_; co = 256; }
                    *reinterpret_cast<float2*>(&Cout[(size_t)r2 * 384 + co + colb])
                        = make_float2(v0, v1);
                } else if (EPI == 7) {
                    if (colb < 256) {
                        v0 = to_tf32(0.5f * v0 * (1.f + erff(v0 * 0.70710678f)));
                        v1 = to_tf32(0.5f * v1 * (1.f + erff(v1 * 0.70710678f)));
                        *reinterpret_cast<float2*>(&Cout[(size_t)row * 256 + colb])
                            = make_float2(v0, v1);
                    } else if (colb < 384) {
                        *reinterpret_cast<float2*>(&Cout2[(size_t)row * 128 + colb - 256])
                            = make_float2(v0, v1);
                    } else {
                        *reinterpret_cast<float2*>(&Cout3[(size_t)row * 128 + colb - 384])
                            = make_float2(v0, v1);
                    }
                }
            }
        }
    }
}

// ---------------------------------------------------------------------------
// 2b) Small FFMA SGEMM (288-row pooled GEMM only; W is [K][N] original)
// ---------------------------------------------------------------------------
__global__ __launch_bounds__(256)
void sgemm_small(const float* __restrict__ A, const float* __restrict__ Wm,
                 const float* __restrict__ bias, float* __restrict__ Cout,
                 int M, int N, int K)
{
    __shared__ float As[16][132];
    __shared__ float Ws[16][64];
    int tid = threadIdx.x;
    int bm = blockIdx.y * 128;
    int bn = blockIdx.x * 64;
    int tx = tid & 15, ty = tid >> 4;
    float acc[8][4];
    #pragma unroll
    for (int i = 0; i < 8; ++i)
        #pragma unroll
        for (int j = 0; j < 4; ++j) acc[i][j] = 0.f;
    int aRow = tid >> 2;
    int aK   = (tid & 3) << 2;
    int wRow = tid >> 4;
    int wCol = (tid & 15) << 2;
    for (int k0 = 0; k0 < K; k0 += 16) {
        #pragma unroll
        for (int r = 0; r < 2; ++r) {
            int row = bm + aRow + r * 64;
            float4 v = make_float4(0.f, 0.f, 0.f, 0.f);
            if (row < M)
                v = *reinterpret_cast<const float4*>(A + (size_t)row * K + k0 + aK);
            As[aK + 0][aRow + r * 64] = v.x;
            As[aK + 1][aRow + r * 64] = v.y;
            As[aK + 2][aRow + r * 64] = v.z;
            As[aK + 3][aRow + r * 64] = v.w;
        }
        *reinterpret_cast<float4*>(&Ws[wRow][wCol]) =
            *reinterpret_cast<const float4*>(Wm + (size_t)(k0 + wRow) * N + bn + wCol);
        __syncthreads();
        #pragma unroll
        for (int kk = 0; kk < 16; ++kk) {
            float a[8], bf[4];
            #pragma unroll
            for (int i = 0; i < 8; ++i) a[i] = As[kk][ty * 8 + i];
            #pragma unroll
            for (int j = 0; j < 4; ++j) bf[j] = Ws[kk][tx * 4 + j];
            #pragma unroll
            for (int i = 0; i < 8; ++i)
                #pragma unroll
                for (int j = 0; j < 4; ++j)
                    acc[i][j] = fmaf(a[i], bf[j], acc[i][j]);
        }
        __syncthreads();
    }
    #pragma unroll
    for (int i = 0; i < 8; ++i) {
        int row = bm + ty * 8 + i;
        if (row >= M) continue;
        #pragma unroll
        for (int j = 0; j < 4; ++j) {
            int col = bn + tx * 4 + j;
            Cout[(size_t)row * N + col] = acc[i][j] + bias[col];
        }
    }
}

// ---------------------------------------------------------------------------
// 4) Attention (online softmax, split over keys) + combine.
// ---------------------------------------------------------------------------
__global__ __launch_bounds__(288)
void attn_partial(const float* __restrict__ kv, const float* __restrict__ mq_all,
                  float* __restrict__ pmax, float* __restrict__ psum,
                  float* __restrict__ pacc)
{
    __shared__ float ks[CHUNK_ * KSTR_];
    __shared__ float vs[CHUNK_ * KSTR_];
    int b = blockIdx.z, head = blockIdx.y, sp = blockIdx.x;
    int tid = threadIdx.x;
    int q = tid >> 3, j = tid & 7;
    float mq[16];
    #pragma unroll
    for (int d = 0; d < 16; ++d)
        mq[d] = mq_all[(size_t)(b * 36 + q) * 128 + head * 16 + d] * 0.25f;
    float mx = -INFINITY, sm = 0.f;
    float acc[16];
    #pragma unroll
    for (int d = 0; d < 16; ++d) acc[d] = 0.f;
    int kb = sp * KPS_;
    for (int c0 = 0; c0 < NCHUNK_; ++c0) {
        int pos0 = kb + c0 * CHUNK_;
        if (tid < CHUNK_ * 4) {
            int key = tid >> 2, d4 = tid & 3;
            size_t gb = ((size_t)b * HW_ + pos0 + key) * 256 + head * 16 + d4 * 4;
            *reinterpret_cast<float4*>(&ks[key * KSTR_ + d4 * 4]) =
                *reinterpret_cast<const float4*>(kv + gb);
            *reinterpret_cast<float4*>(&vs[key * KSTR_ + d4 * 4]) =
                *reinterpret_cast<const float4*>(kv + gb + 128);
        }
        __syncthreads();
        for (int key = j; key < CHUNK_; key += 8) {
            const float4* k4 = reinterpret_cast<const float4*>(&ks[key * KSTR_]);
            float4 ka = k4[0], kb2 = k4[1], kc = k4[2], kd = k4[3];
            float s = mq[0] * ka.x;
            s = fmaf(mq[1],  ka.y,  s); s = fmaf(mq[2],  ka.z,  s);
            s = fmaf(mq[3],  ka.w,  s); s = fmaf(mq[4],  kb2.x, s);
            s = fmaf(mq[5],  kb2.y, s); s = fmaf(mq[6],  kb2.z, s);
            s = fmaf(mq[7],  kb2.w, s); s = fmaf(mq[8],  kc.x,  s);
            s = fmaf(mq[9],  kc.y,  s); s = fmaf(mq[10], kc.z,  s);
            s = fmaf(mq[11], kc.w,  s); s = fmaf(mq[12], kd.x,  s);
            s = fmaf(mq[13], kd.y,  s); s = fmaf(mq[14], kd.z,  s);
            s = fmaf(mq[15], kd.w,  s);
            const float4* v4 = reinterpret_cast<const float4*>(&vs[key * KSTR_]);
            float4 va = v4[0], vb = v4[1], vc = v4[2], vd = v4[3];
            if (s <= mx) {
                float p = __expf(s - mx);
                sm += p;
                acc[0]  = fmaf(p, va.x, acc[0]);  acc[1]  = fmaf(p, va.y, acc[1]);
                acc[2]  = fmaf(p, va.z, acc[2]);  acc[3]  = fmaf(p, va.w, acc[3]);
                acc[4]  = fmaf(p, vb.x, acc[4]);  acc[5]  = fmaf(p, vb.y, acc[5]);
                acc[6]  = fmaf(p, vb.z, acc[6]);  acc[7]  = fmaf(p, vb.w, acc[7]);
                acc[8]  = fmaf(p, vc.x, acc[8]);  acc[9]  = fmaf(p, vc.y, acc[9]);
                acc[10] = fmaf(p, vc.z, acc[10]); acc[11] = fmaf(p, vc.w, acc[11]);
                acc[12] = fmaf(p, vd.x, acc[12]); acc[13] = fmaf(p, vd.y, acc[13]);
                acc[14] = fmaf(p, vd.z, acc[14]); acc[15] = fmaf(p, vd.w, acc[15]);
            } else {
                float cr = __expf(mx - s);
                sm = fmaf(sm, cr, 1.f);
                acc[0]  = fmaf(acc[0],  cr, va.x); acc[1]  = fmaf(acc[1],  cr, va.y);
                acc[2]  = fmaf(acc[2],  cr, va.z); acc[3]  = fmaf(acc[3],  cr, va.w);
                acc[4]  = fmaf(acc[4],  cr, vb.x); acc[5]  = fmaf(acc[5],  cr, vb.y);
                acc[6]  = fmaf(acc[6],  cr, vb.z); acc[7]  = fmaf(acc[7],  cr, vb.w);
                acc[8]  = fmaf(acc[8],  cr, vc.x); acc[9]  = fmaf(acc[9],  cr, vc.y);
                acc[10] = fmaf(acc[10], cr, vc.z); acc[11] = fmaf(acc[11], cr, vc.w);
                acc[12] = fmaf(acc[12], cr, vd.x); acc[13] = fmaf(acc[13], cr, vd.y);
                acc[14] = fmaf(acc[14], cr, vd.z); acc[15] = fmaf(acc[15], cr, vd.w);
                mx = s;
            }
        }
        __syncthreads();
    }
    #pragma unroll
    for (int o = 4; o > 0; o >>= 1) {
        float omx = __shfl_xor_sync(0xffffffffu, mx, o);
        float osm = __shfl_xor_sync(0xffffffffu, sm, o);
        float nm = fmaxf(mx, omx);
        float c1 = __expf(mx - nm), c2 = __expf(omx - nm);
        sm = sm * c1 + osm * c2;
        #pragma unroll
        for (int d = 0; d < 16; ++d) {
            float oa = __shfl_xor_sync(0xffffffffu, acc[d], o);
            acc[d] = acc[d] * c1 + oa * c2;
        }
        mx = nm;
    }
    int pi = (b * NH_ + head) * 36 + q;
    if (j == 0) {
        pmax[pi * SPLIT_ + sp] = mx;
        psum[pi * SPLIT_ + sp] = sm;
        #pragma unroll
        for (int d = 0; d < 16; ++d)
            pacc[((size_t)pi * SPLIT_ + sp) * 16 + d] = acc[d];
    }
}

__global__ void attn_combine(const float* __restrict__ pmax, const float* __restrict__ psum,
                             const float* __restrict__ pacc, float* __restrict__ sm_out)
{
    int idx = blockIdx.x * blockDim.x + threadIdx.x;
    if (idx >= B_ * NH_ * 36 * 16) return;
    int d  = idx & 15;
    int q  = (idx >> 4) % 36;
    int bh = idx / (16 * 36);
    int pi = bh * 36 + q;
    float gm = -INFINITY;
    #pragma unroll
    for (int s = 0; s < SPLIT_; ++s) gm = fmaxf(gm, pmax[pi * SPLIT_ + s]);
    float ts = 0.f, tv = 0.f;
    #pragma unroll
    for (int s = 0; s < SPLIT_; ++s) {
        float c = __expf(pmax[pi * SPLIT_ + s] - gm);
        ts += c * psum[pi * SPLIT_ + s];
        tv += c * pacc[((size_t)pi * SPLIT_ + s) * 16 + d];
    }
    int b = bh >> 3, head = bh & 7;
    sm_out[(size_t)(b * 128 + head * 16 + d) * 36 + q] = tv / ts;
}

// ---------------------------------------------------------------------------
// 5) Bilinear upsample (B,128,6,6) -> cat[:, 0:128], tf32-rounded
// ---------------------------------------------------------------------------
__global__ void upsample_kernel(const float* __restrict__ sm_in, float* __restrict__ cat)
{
    __shared__ float s[36][128];
    int b = blockIdx.y;
    for (int idx = threadIdx.x; idx < 36 * 128; idx += 128) {
        int q = idx >> 7, ch = idx & 127;
        s[q][ch] = sm_in[(size_t)(b * 128 + ch) * 36 + q];
    }
    __syncthreads();
    int ch = threadIdx.x;
    int p0 = blockIdx.x * 64;
    for (int k = 0; k < 64; ++k) {
        int p = p0 + k;
        if (p >= HW_) return;
        int h = p / 132, w = p - h * 132;
        float sy = (h + 0.5f) * (1.f / 22.f) - 0.5f;
        float sx = (w + 0.5f) * (1.f / 22.f) - 0.5f;
        float fy0 = floorf(sy), fx0 = floorf(sx);
        float fy = sy - fy0, fx = sx - fx0;
        int y0 = (int)fy0, x0 = (int)fx0;
        int y1 = min(y0 + 1, 5), x1 = min(x0 + 1, 5);
        y0 = max(y0, 0); x0 = max(x0, 0);
        float v00 = s[y0 * 6 + x0][ch], v01 = s[y0 * 6 + x1][ch];
        float v10 = s[y1 * 6 + x0][ch], v11 = s[y1 * 6 + x1][ch];
        float v = (1.f - fy) * ((1.f - fx) * v00 + fx * v01)
                + fy * ((1.f - fx) * v10 + fx * v11);
        cat[((size_t)b * HW_ + p) * 384 + ch] = to_tf32(v);
    }
}

// ---------------------------------------------------------------------------
// 6) Depthwise 7x7 conv, NHWC channels-inner, batched over 2B images;
//    output tf32-rounded
// ---------------------------------------------------------------------------
__global__ __launch_bounds__(256)
void dwconv_kernel(const float* __restrict__ in, const float* __restrict__ wgt,
                   const float* __restrict__ cbias, float* __restrict__ out)
{
    __shared__ float s[10][22][32];
    __shared__ float wsm[32][49];
    int wt = blockIdx.x, ht = blockIdx.y;
    int bz = blockIdx.z;
    int b = bz >> 2, cg = bz & 3;    // b in [0, 2*B_)
    int h0 = ht * 4, w0 = wt * 16;
    int tid = threadIdx.x;
    for (int idx = tid; idx < 32 * 49; idx += 256) {
        int ch = idx / 49, t = idx - ch * 49;
        wsm[ch][t] = wgt[(cg * 32 + ch) * 49 + t];
    }
    const float* inb = in + (size_t)b * HW_ * 128;
    for (int idx = tid; idx < 10 * 22 * 32; idx += 256) {
        int ch = idx & 31;
        int r  = idx >> 5;
        int lw = r % 22, lh = r / 22;
        int gh = h0 - 3 + lh, gw = w0 - 3 + lw;
        float v = 0.f;
        if (gh >= 0 && gh < 132 && gw >= 0 && gw < 132)
            v = inb[(size_t)(gh * 132 + gw) * 128 + cg * 32 + ch];
        s[lh][lw][ch] = v;
    }
    __syncthreads();
    int ch = tid & 31;
    int pg = tid >> 5;
    float acc[8];
    #pragma unroll
    for (int i = 0; i < 8; ++i) acc[i] = 0.f;
    #pragma unroll
    for (int dy = 0; dy < 7; ++dy)
        #pragma unroll
        for (int dx = 0; dx < 7; ++dx) {
            float wv = wsm[ch][dy * 7 + dx];
            #pragma unroll
            for (int pi = 0; pi < 8; ++pi) {
                int posid = pg + pi * 8;
                int lh = posid >> 4, lw = posid & 15;
                acc[pi] = fmaf(wv, s[lh + dy][lw + dx][ch], acc[pi]);
            }
        }
    float bv = cbias[cg * 32 + ch];
    #pragma unroll
    for (int pi = 0; pi < 8; ++pi) {
        int posid = pg + pi * 8;
        int lh = posid >> 4, lw = posid & 15;
        int gw = w0 + lw;
        if (gw < 132)
            out[((size_t)b * HW_ + (h0 + lh) * 132 + gw) * 128 + cg * 32 + ch]
                = to_tf32(acc[pi] + bv);
    }
}

// ---------------------------------------------------------------------------
// Launcher — two-stream fork/join inside graph capture
// ---------------------------------------------------------------------------
extern "C" void kernel_launch(void* const* d_in, const int* in_sizes, int n_in,
                              void* d_out, int out_size)
{
    (void)in_sizes; (void)n_in; (void)out_size;
    const float* x       = (const float*)d_in[0];
    const float* x_e     = (const float*)d_in[1];
    const float* norm_w  = (const float*)d_in[2];
    const float* norm_b  = (const float*)d_in[3];
    const float* norme_w = (const float*)d_in[4];
    const float* norme_b = (const float*)d_in[5];
    const float* l_w     = (const float*)d_in[6];
    const float* l_b     = (const float*)d_in[7];
    const float* kv_w    = (const float*)d_in[8];
    const float* kv_b    = (const float*)d_in[9];
    const float* xe_w    = (const float*)d_in[10];
    const float* xe_b    = (const float*)d_in[11];
    const float* q_w     = (const float*)d_in[12];
    const float* q_b     = (const float*)d_in[13];
    const float* ef_w    = (const float*)d_in[14];
    const float* ef_b    = (const float*)d_in[15];
    const float* ec_w    = (const float*)d_in[16];
    const float* ec_b    = (const float*)d_in[17];
    const float* eb_w    = (const float*)d_in[18];
    const float* eb_b    = (const float*)d_in[19];
    const float* proj_w  = (const float*)d_in[20];
    const float* proj_b  = (const float*)d_in[21];
    const float* proje_w = (const float*)d_in[22];
    const float* proje_b = (const float*)d_in[23];

    float* base = nullptr;
    cudaGetSymbolAddress((void**)&base, g_scratch);
    float* xc    = base + OFF_XC;
    float* xec   = base + OFF_XEC;
    float* xg    = base + OFF_XG;
    float* kvb   = base + OFF_KV;
    float* cat   = base + OFF_CAT;
    float* tq    = base + OFF_TQ;    // [q_xc ; q_xec]
    float* tef   = base + OFF_TEF;   // [ef_xec ; ef_xc]
    float* tcv   = base + OFF_TCV;   // conv outputs, same row order as tef
    float* pool  = base + OFF_POOL;
    float* mbuf  = base + OFF_MM;
    float* smalb = base + OFF_SMALL;
    float* pmax  = base + OFF_PMAX;
    float* psum  = base + OFF_PSUM;
    float* pacc  = base + OFF_PACC;
    float* wbig  = base + OFF_WBIG;
    float* wkv_t = base + OFF_WKV;
    float* web_t = base + OFF_WEB;
    float* wproj_t = base + OFF_WPROJ;
    float* bbig  = base + OFF_BBIG;
    float* bqef  = base + OFF_BQEF;
    float* bproj = base + OFF_BPROJ;
    float* wqef_t = wbig + 256 * 256;   // rows 256..511 of wbig == q|ef fused

    float* outp = (float*)d_out;
    float* oute = outp + SZ_BIG;

    cudaStream_t s2;
    cudaStreamCreateWithFlags(&s2, cudaStreamNonBlocking);
    cudaEvent_t evFork, evPrep, evKV, evAttn;
    cudaEventCreateWithFlags(&evFork, cudaEventDisableTiming);
    cudaEventCreateWithFlags(&evPrep, cudaEventDisableTiming);
    cudaEventCreateWithFlags(&evKV,   cudaEventDisableTiming);
    cudaEventCreateWithFlags(&evAttn, cudaEventDisableTiming);

    dim3 lnG((HW_ + 31) / 32, B_, 2);

    // ---- fork 1: weight/bias prep on s2, overlapped with memset + LN -------
    cudaEventRecord(evFork, 0);
    cudaStreamWaitEvent(s2, evFork, 0);
    tr_round3<<<(256 * 512 + 255) / 256, 256, 0, s2>>>(l_w, q_w, ef_w, wbig);
    tr_round <<<(256 * 256 + 255) / 256, 256, 0, s2>>>(kv_w, wkv_t, 256, 256);
    prep_bias<<<2, 256, 0, s2>>>(l_b, q_b, ef_b, proj_b, proje_b, bbig, bqef, bproj);
    tr_round <<<(128 * 128 + 255) / 256, 256, 0, s2>>>(eb_w, web_t, 128, 128);
    tr_round2<<<(384 * 512 + 255) / 256, 256, 0, s2>>>(proj_w, proje_w, wproj_t, 384, 256);
    cudaEventRecord(evPrep, s2);

    // main: zero pooled accumulator + dual LayerNorm (independent of prep)
    cudaMemsetAsync(pool, 0, (size_t)B_ * 36 * 512 * sizeof(float));
    ln2_kernel<<<lnG, 256>>>(x, x_e, norm_w, norm_b, norme_w, norme_b,
                             xc, xec, pool);

    // join prep before the first GEMM that uses the transformed weights
    cudaStreamWaitEvent(0, evPrep, 0);

    // fused xc GEMM (N=512): gelu->xg | q_xc->tq[0:M] | ef_xc->tef[M:2M]
    tgemm<7><<<dim3(4, 1089), 256>>>(xc, wbig, bbig, nullptr,
                                     xg, tq, tef + SZ_HALF, M_, 512, 256);
    // kv GEMM
    tgemm<0><<<dim3(2, 1089), 256>>>(xg, wkv_t, kv_b, nullptr,
                                     kvb, nullptr, nullptr, M_, 256, 256);
    cudaEventRecord(evKV, 0);

    // ---- fork 2: GFA attention chain on s2 (needs pool + kvb only) --------
    cudaStreamWaitEvent(s2, evKV, 0);
    sgemm_small<<<dim3(2, 3), 256, 0, s2>>>(pool, xe_w, xe_b, mbuf,
                                            B_ * 36, 128, 512);
    attn_partial<<<dim3(SPLIT_, NH_, B_), 288, 0, s2>>>(kvb, mbuf,
                                                        pmax, psum, pacc);
    attn_combine<<<(B_ * NH_ * 36 * 16 + 255) / 256, 256, 0, s2>>>(
        pmax, psum, pacc, smalb);
    upsample_kernel<<<dim3((HW_ + 63) / 64, B_), 128, 0, s2>>>(smalb, cat);
    cudaEventRecord(evAttn, s2);

    // main (concurrent with s2): xec q|ef GEMM, batched dwconv, merged eb GEMM
    tgemm<5><<<dim3(2, 1089), 256>>>(xec, wqef_t, bqef, nullptr,
                                     tq + SZ_HALF, tef, nullptr, M_, 256, 256);
    dwconv_kernel<<<dim3(9, 33, 2 * B_ * 4), 256>>>(tef, ec_w, ec_b, tcv);
    tgemm<6><<<dim3(1, 2178), 256>>>(tcv, web_t, eb_b, tq,
                                     cat, nullptr, nullptr, 2 * M_, 128, 128);

    // join attention chain before the projections read all of cat
    cudaStreamWaitEvent(0, evAttn, 0);

    // fused projections, NCHW outputs split at col 256
    tgemm<4><<<dim3(4, 1089), 256>>>(cat, wproj_t, bproj, nullptr,
                                     outp, oute, nullptr, M_, 512, 384);
}